// round 11
// baseline (speedup 1.0000x reference)
#include <cuda_runtime.h>
#include <cuda_fp16.h>
#include <cstdint>

#define N_NODES 100000
#define N_EDGES 1600000
#define D 128
#define EPS 1e-5f

// ---------------- scratch ----------------
__device__ float g_aggr[(size_t)N_NODES * D];
__device__ float g_h[(size_t)N_NODES * D];
__device__ __half g_x16[(size_t)N_NODES * D];   // fp16 copy of x for gathers
__device__ float g_sum[D];
__device__ float g_sumsq[D];
__device__ int   g_idx_is64;
__device__ __half gW_h[256 * 128];   // rows 0-127 W_root, 128-255 W_rel (fp16)

// ---------------- helpers ----------------
__device__ __forceinline__ uint32_t smem_u32(const void* p) {
    uint32_t a;
    asm("{ .reg .u64 t; cvta.to.shared.u64 t, %1; cvt.u32.u64 %0, t; }"
        : "=r"(a) : "l"(p));
    return a;
}
__device__ __forceinline__ void ldsm_x4_t(uint32_t& r0, uint32_t& r1,
                                          uint32_t& r2, uint32_t& r3, uint32_t a) {
    asm volatile("ldmatrix.sync.aligned.m8n8.x4.trans.shared.b16 {%0,%1,%2,%3}, [%4];"
                 : "=r"(r0), "=r"(r1), "=r"(r2), "=r"(r3) : "r"(a));
}
__device__ __forceinline__ void mma_f16(float* c, const uint32_t* a, const uint32_t* b) {
    asm volatile("mma.sync.aligned.m16n8k16.row.col.f32.f16.f16.f32 "
                 "{%0,%1,%2,%3}, {%4,%5,%6,%7}, {%8,%9}, {%0,%1,%2,%3};"
                 : "+f"(c[0]), "+f"(c[1]), "+f"(c[2]), "+f"(c[3])
                 : "r"(a[0]), "r"(a[1]), "r"(a[2]), "r"(a[3]),
                   "r"(b[0]), "r"(b[1]));
}
__device__ __forceinline__ void split_h(float2 v, uint32_t& hi, uint32_t& lo) {
    __half h0 = __float2half_rn(v.x);
    __half h1 = __float2half_rn(v.y);
    __half2 hp = __halves2half2(h0, h1);
    __half2 lp = __halves2half2(__float2half_rn(v.x - __half2float(h0)),
                                __float2half_rn(v.y - __half2float(h1)));
    hi = *(uint32_t*)&hp;
    lo = *(uint32_t*)&lp;
}
__device__ __forceinline__ void red_add_v4(float* addr, float4 v) {
    asm volatile("red.global.add.v4.f32 [%0], {%1, %2, %3, %4};"
                 :: "l"(addr), "f"(v.x), "f"(v.y), "f"(v.z), "f"(v.w)
                 : "memory");
}

// smem layout (byte offsets in dynamic smem)
#define B_HI   0             // 128 rows * 272 B
#define SM_BIAS 34816        // 128 f32
#define SM_SSUM 35328        // 128 f32
#define SM_SSQ  35840        // 128 f32
#define SMEMSZ  36352

// ---------------- kernel 0: probe dtype + zero stats ----------------
__global__ void probe_kernel(const int* __restrict__ e) {
    __shared__ int nz;
    int t = threadIdx.x;
    if (t == 0) nz = 0;
    if (t < D) { g_sum[t] = 0.f; g_sumsq[t] = 0.f; }
    __syncthreads();
    if (t < 64) {
        int v = e[t * 2 + 1];
        if (v != 0) atomicAdd(&nz, 1);
    }
    __syncthreads();
    if (t == 0) g_idx_is64 = (nz == 0) ? 1 : 0;
}

// ---------------- kernel 1: convert x to fp16 ----------------
__global__ void xconv_kernel(const float* __restrict__ x) {
    int idx = blockIdx.x * blockDim.x + threadIdx.x;   // over groups of 8
    const int n8 = (N_NODES * D) / 8;
    if (idx >= n8) return;
    const float4* src = (const float4*)x + idx * 2;
    float4 a = src[0], b = src[1];
    __half2 h0 = __halves2half2(__float2half_rn(a.x), __float2half_rn(a.y));
    __half2 h1 = __halves2half2(__float2half_rn(a.z), __float2half_rn(a.w));
    __half2 h2 = __halves2half2(__float2half_rn(b.x), __float2half_rn(b.y));
    __half2 h3 = __halves2half2(__float2half_rn(b.z), __float2half_rn(b.w));
    uint4 o = make_uint4(*(uint32_t*)&h0, *(uint32_t*)&h1,
                         *(uint32_t*)&h2, *(uint32_t*)&h3);
    ((uint4*)g_x16)[idx] = o;
}

// ---------------- kernel 2: convert weights to fp16 (once) ----------------
__global__ void wconv_kernel(const float* __restrict__ W_root,
                             const float* __restrict__ W_rel) {
    int idx = blockIdx.x * blockDim.x + threadIdx.x;   // 8192 threads
#pragma unroll
    for (int p = idx; p < 16384; p += 8192) {
        int k = p >> 6;
        int n2 = (p & 63) * 2;
        const float* W = (k < 128) ? (W_root + k * 128 + n2)
                                   : (W_rel + (k - 128) * 128 + n2);
        float2 v = *(const float2*)W;
        __half2 h = __halves2half2(__float2half_rn(v.x), __float2half_rn(v.y));
        *(uint32_t*)((char*)gW_h + (size_t)(k * 128 + n2) * 2) = *(uint32_t*)&h;
    }
}

// ---------------- kernel 3: scatter (fp16 gather, fp32 RED) ----------
#define EB 8                    // edges per warp-iteration
#define SC_BLOCKS 592           // 4 per SM

__global__ void __launch_bounds__(256, 4)
scatter_kernel(const void* __restrict__ edge_index) {
    const int wid = threadIdx.x >> 5;
    const int lane = threadIdx.x & 31;
    const int wglob = blockIdx.x * 8 + wid;
    const int NW = SC_BLOCKS * 8;
    const bool is64 = (g_idx_is64 != 0);

#pragma unroll 1
    for (int it = 0; ; it++) {
        int e0 = (wglob + it * NW) * EB;
        if (e0 >= N_EDGES) break;
        int s[EB], d[EB];
        if (is64) {
            const long long* e = (const long long*)edge_index;
#pragma unroll
            for (int j = 0; j < EB; j++) {
                s[j] = (int)e[e0 + j];
                d[j] = (int)e[N_EDGES + e0 + j];
            }
        } else {
            const int* e = (const int*)edge_index;
            int4 sv0 = *(const int4*)(e + e0);
            int4 sv1 = *(const int4*)(e + e0 + 4);
            int4 dv0 = *(const int4*)(e + N_EDGES + e0);
            int4 dv1 = *(const int4*)(e + N_EDGES + e0 + 4);
            s[0] = sv0.x; s[1] = sv0.y; s[2] = sv0.z; s[3] = sv0.w;
            s[4] = sv1.x; s[5] = sv1.y; s[6] = sv1.z; s[7] = sv1.w;
            d[0] = dv0.x; d[1] = dv0.y; d[2] = dv0.z; d[3] = dv0.w;
            d[4] = dv1.x; d[5] = dv1.y; d[6] = dv1.z; d[7] = dv1.w;
        }
        int cnt = N_EDGES - e0; if (cnt > EB) cnt = EB;
        uint2 hv[EB];
#pragma unroll
        for (int j = 0; j < EB; j++) {
            bool ok = (j < cnt) && ((unsigned)s[j] < N_NODES);
            hv[j] = ok ? *((const uint2*)(g_x16 + (size_t)s[j] * D) + lane)
                       : make_uint2(0u, 0u);
        }
#pragma unroll
        for (int j = 0; j < EB; j++) {
            if ((j < cnt) && ((unsigned)s[j] < N_NODES) && ((unsigned)d[j] < N_NODES)) {
                float2 f0 = __half22float2(*(__half2*)&hv[j].x);
                float2 f1 = __half22float2(*(__half2*)&hv[j].y);
                red_add_v4(g_aggr + (size_t)d[j] * D + lane * 4,
                           make_float4(f0.x, f0.y, f1.x, f1.y));
            }
        }
    }
}

// ---------------- kernel 4: K=256 GEMM + bias + BN stats ------------------
__global__ void __launch_bounds__(256, 2)
gemmAB_kernel(const float* __restrict__ x, const float* __restrict__ b_rel) {
    extern __shared__ char smem[];
    const uint32_t sb = smem_u32(smem);
    const int tid = threadIdx.x;
    const int w = tid >> 5;
    const int lid = tid & 31;
    const int m0 = blockIdx.x * 128;

    if (tid < 128) {
        ((float*)(smem + SM_BIAS))[tid] = b_rel[tid];
        ((float*)(smem + SM_SSUM))[tid] = 0.f;
        ((float*)(smem + SM_SSQ))[tid]  = 0.f;
    }

    float acc[16][4];
#pragma unroll
    for (int q = 0; q < 16; q++)
#pragma unroll
        for (int c = 0; c < 4; c++) acc[q][c] = 0.f;

    const int r = lid >> 2;
    const int cq = (lid & 3) * 2;
    const int m = m0 + w * 16 + r;
    const bool v0 = m < N_NODES;
    const bool v1 = (m + 8) < N_NODES;
    const float2 fz = make_float2(0.f, 0.f);

#pragma unroll 1
    for (int half = 0; half < 2; half++) {
#pragma unroll
        for (int i = 0; i < 8; i++) {
            int ch = tid + i * 256;
            int row = ch >> 4, c16 = ch & 15;
            size_t gsrc = (size_t)((half * 128 + row) * 128 + c16 * 8) * 2;
            *(uint4*)(smem + B_HI + row * 272 + c16 * 16) =
                *(const uint4*)((const char*)gW_h + gsrc);
        }
        __syncthreads();

        const float* A = half ? g_aggr : x;
        const float* pr0 = A + (size_t)m * D + cq;
        const float* pr1 = A + (size_t)(m + 8) * D + cq;

#pragma unroll
        for (int s = 0; s < 8; s++) {
            const int ko = s * 16;
            float2 x00 = v0 ? *(const float2*)(pr0 + ko) : fz;
            float2 x10 = v1 ? *(const float2*)(pr1 + ko) : fz;
            float2 x01 = v0 ? *(const float2*)(pr0 + ko + 8) : fz;
            float2 x11 = v1 ? *(const float2*)(pr1 + ko + 8) : fz;
            uint32_t ah[4], al[4];
            split_h(x00, ah[0], al[0]);
            split_h(x10, ah[1], al[1]);
            split_h(x01, ah[2], al[2]);
            split_h(x11, ah[3], al[3]);

            const uint32_t rowa = sb + (uint32_t)((s * 16 + (lid & 15)) * 272
                                                  + (lid >> 4) * 16);
#pragma unroll
            for (int q8 = 0; q8 < 8; q8++) {
                uint32_t bh[4];
                ldsm_x4_t(bh[0], bh[1], bh[2], bh[3],
                          rowa + (uint32_t)(q8 * 32) + B_HI);
                float* c0 = acc[q8 * 2];
                float* c1 = acc[q8 * 2 + 1];
                mma_f16(c0, ah, bh);
                mma_f16(c0, al, bh);
                mma_f16(c1, ah, bh + 2);
                mma_f16(c1, al, bh + 2);
            }
        }
        __syncthreads();
    }

    // ---- epilogue: bias + direct store + BN stats (shuffle-reduced) ----
    const float* bs = (const float*)(smem + SM_BIAS);
    float* ssum = (float*)(smem + SM_SSUM);
    float* ssq  = (float*)(smem + SM_SSQ);
#pragma unroll
    for (int q = 0; q < 16; q++) {
        int n = q * 8 + cq;
        float b0 = bs[n], b1 = bs[n + 1];
        float s0 = 0.f, s1 = 0.f, q0 = 0.f, q1 = 0.f;
        if (v0) {
            float2 o = make_float2(acc[q][0] + b0, acc[q][1] + b1);
            *(float2*)(g_h + (size_t)m * D + n) = o;
            s0 += o.x; s1 += o.y;
            q0 += o.x * o.x; q1 += o.y * o.y;
        }
        if (v1) {
            float2 o = make_float2(acc[q][2] + b0, acc[q][3] + b1);
            *(float2*)(g_h + (size_t)(m + 8) * D + n) = o;
            s0 += o.x; s1 += o.y;
            q0 += o.x * o.x; q1 += o.y * o.y;
        }
#pragma unroll
        for (int mk = 4; mk <= 16; mk <<= 1) {
            s0 += __shfl_xor_sync(0xffffffffu, s0, mk);
            s1 += __shfl_xor_sync(0xffffffffu, s1, mk);
            q0 += __shfl_xor_sync(0xffffffffu, q0, mk);
            q1 += __shfl_xor_sync(0xffffffffu, q1, mk);
        }
        if ((lid >> 2) == 0) {
            atomicAdd(&ssum[n],     s0);
            atomicAdd(&ssum[n + 1], s1);
            atomicAdd(&ssq[n],      q0);
            atomicAdd(&ssq[n + 1],  q1);
        }
    }
    __syncthreads();
    if (tid < 128) {
        atomicAdd(&g_sum[tid],   ssum[tid]);
        atomicAdd(&g_sumsq[tid], ssq[tid]);
    }
}

// ---------------- fused finalize + normalize + ReLU ----------------
__global__ void norm_kernel(const float* __restrict__ gamma,
                            const float* __restrict__ beta,
                            float* __restrict__ out) {
    __shared__ float ssc[D], ssh[D];
    int t = threadIdx.x;
    if (t < D) {
        float inv_n = 1.0f / (float)N_NODES;
        float mean = g_sum[t] * inv_n;
        float var = g_sumsq[t] * inv_n - mean * mean;
        float sc = gamma[t] * rsqrtf(var + EPS);
        ssc[t] = sc;
        ssh[t] = beta[t] - mean * sc;
    }
    __syncthreads();
    int idx = blockIdx.x * blockDim.x + t;
    const int n4 = (N_NODES * D) / 4;
    if (idx >= n4) return;
    int c4 = (idx & (D / 4 - 1)) * 4;
    float4 h = ((const float4*)g_h)[idx];
    float4 o;
    o.x = fmaxf(h.x * ssc[c4 + 0] + ssh[c4 + 0], 0.f);
    o.y = fmaxf(h.y * ssc[c4 + 1] + ssh[c4 + 1], 0.f);
    o.z = fmaxf(h.z * ssc[c4 + 2] + ssh[c4 + 2], 0.f);
    o.w = fmaxf(h.w * ssc[c4 + 3] + ssh[c4 + 3], 0.f);
    ((float4*)out)[idx] = o;
}

// ---------------- launch ----------------
extern "C" void kernel_launch(void* const* d_in, const int* in_sizes, int n_in,
                              void* d_out, int out_size) {
    const float* x      = (const float*)d_in[0];
    const void*  eidx   = d_in[1];
    const float* W_root = (const float*)d_in[2];
    const float* W_rel  = (const float*)d_in[3];
    const float* b_rel  = (const float*)d_in[4];
    const float* gamma  = (const float*)d_in[5];
    const float* beta   = (const float*)d_in[6];
    float*       out    = (float*)d_out;

    cudaFuncSetAttribute(gemmAB_kernel,
                         cudaFuncAttributeMaxDynamicSharedMemorySize, SMEMSZ);

    // zero g_aggr via a memset node (no allocation; graph-capturable)
    void* aggr_ptr = nullptr;
    cudaGetSymbolAddress(&aggr_ptr, g_aggr);
    cudaMemsetAsync(aggr_ptr, 0, (size_t)N_NODES * D * sizeof(float));

    probe_kernel<<<1, 128>>>((const int*)eidx);

    const int n8 = (N_NODES * D) / 8;
    xconv_kernel<<<(n8 + 255) / 256, 256>>>(x);

    wconv_kernel<<<32, 256>>>(W_root, W_rel);

    scatter_kernel<<<SC_BLOCKS, 256>>>(eidx);

    gemmAB_kernel<<<(N_NODES + 127) / 128, 256, SMEMSZ>>>(x, b_rel);

    const int n4 = (N_NODES * D) / 4;
    norm_kernel<<<(n4 + 255) / 256, 256>>>(gamma, beta, out);
}

// round 12
// speedup vs baseline: 1.0644x; 1.0644x over previous
#include <cuda_runtime.h>
#include <cuda_fp16.h>
#include <cstdint>

#define N_NODES 100000
#define N_EDGES 1600000
#define D 128
#define EPS 1e-5f

// ---------------- scratch ----------------
__device__ float g_aggr[(size_t)N_NODES * D];
__device__ float g_h[(size_t)N_NODES * D];
__device__ __half g_x16[(size_t)N_NODES * D];   // fp16 copy of x
__device__ float g_sum[D];
__device__ float g_sumsq[D];
__device__ int   g_idx_is64;
__device__ __half gW_h[256 * 128];   // rows 0-127 W_root, 128-255 W_rel (fp16)

// ---------------- helpers ----------------
__device__ __forceinline__ uint32_t smem_u32(const void* p) {
    uint32_t a;
    asm("{ .reg .u64 t; cvta.to.shared.u64 t, %1; cvt.u32.u64 %0, t; }"
        : "=r"(a) : "l"(p));
    return a;
}
__device__ __forceinline__ void ldsm_x4_t(uint32_t& r0, uint32_t& r1,
                                          uint32_t& r2, uint32_t& r3, uint32_t a) {
    asm volatile("ldmatrix.sync.aligned.m8n8.x4.trans.shared.b16 {%0,%1,%2,%3}, [%4];"
                 : "=r"(r0), "=r"(r1), "=r"(r2), "=r"(r3) : "r"(a));
}
__device__ __forceinline__ void mma_f16(float* c, const uint32_t* a, const uint32_t* b) {
    asm volatile("mma.sync.aligned.m16n8k16.row.col.f32.f16.f16.f32 "
                 "{%0,%1,%2,%3}, {%4,%5,%6,%7}, {%8,%9}, {%0,%1,%2,%3};"
                 : "+f"(c[0]), "+f"(c[1]), "+f"(c[2]), "+f"(c[3])
                 : "r"(a[0]), "r"(a[1]), "r"(a[2]), "r"(a[3]),
                   "r"(b[0]), "r"(b[1]));
}
__device__ __forceinline__ void split_h(float2 v, uint32_t& hi, uint32_t& lo) {
    __half h0 = __float2half_rn(v.x);
    __half h1 = __float2half_rn(v.y);
    __half2 hp = __halves2half2(h0, h1);
    __half2 lp = __halves2half2(__float2half_rn(v.x - __half2float(h0)),
                                __float2half_rn(v.y - __half2float(h1)));
    hi = *(uint32_t*)&hp;
    lo = *(uint32_t*)&lp;
}
__device__ __forceinline__ void red_add_v4(float* addr, float4 v) {
    asm volatile("red.global.add.v4.f32 [%0], {%1, %2, %3, %4};"
                 :: "l"(addr), "f"(v.x), "f"(v.y), "f"(v.z), "f"(v.w)
                 : "memory");
}

// smem layout (byte offsets in dynamic smem)
#define B_HI   0             // 128 rows * 272 B
#define SM_BIAS 34816        // 128 f32
#define SM_SSUM 35328        // 128 f32
#define SM_SSQ  35840        // 128 f32
#define SMEMSZ  36352

// ---------------- kernel 1: fused prologue ----------------
// grid covers (N_NODES*D)/8 threads:
//  - convert 8 x values -> g_x16, zero 8 aggr values
//  - first 8192 threads: convert weights (2 pairs each)
//  - block 0: probe edge dtype + zero stats
__global__ void prologue_kernel(const float* __restrict__ x,
                                const float* __restrict__ W_root,
                                const float* __restrict__ W_rel,
                                const int* __restrict__ e) {
    const int tid = threadIdx.x;
    const int idx = blockIdx.x * 256 + tid;
    const int n8 = (N_NODES * D) / 8;

    if (idx < n8) {
        const float4* src = (const float4*)x + idx * 2;
        float4 a = src[0], b = src[1];
        __half2 h0 = __halves2half2(__float2half_rn(a.x), __float2half_rn(a.y));
        __half2 h1 = __halves2half2(__float2half_rn(a.z), __float2half_rn(a.w));
        __half2 h2 = __halves2half2(__float2half_rn(b.x), __float2half_rn(b.y));
        __half2 h3 = __halves2half2(__float2half_rn(b.z), __float2half_rn(b.w));
        ((uint4*)g_x16)[idx] = make_uint4(*(uint32_t*)&h0, *(uint32_t*)&h1,
                                          *(uint32_t*)&h2, *(uint32_t*)&h3);
        uint4 z = make_uint4(0u, 0u, 0u, 0u);
        ((uint4*)g_aggr)[idx * 2]     = z;
        ((uint4*)g_aggr)[idx * 2 + 1] = z;
    }

    if (idx < 8192) {
#pragma unroll
        for (int p = idx; p < 16384; p += 8192) {
            int k = p >> 6;
            int n2 = (p & 63) * 2;
            const float* W = (k < 128) ? (W_root + k * 128 + n2)
                                       : (W_rel + (k - 128) * 128 + n2);
            float2 v = *(const float2*)W;
            __half2 h = __halves2half2(__float2half_rn(v.x), __float2half_rn(v.y));
            *(uint32_t*)((char*)gW_h + (size_t)(k * 128 + n2) * 2) = *(uint32_t*)&h;
        }
    }

    if (blockIdx.x == 0) {
        __shared__ int nz;
        if (tid == 0) nz = 0;
        if (tid < D) { g_sum[tid] = 0.f; g_sumsq[tid] = 0.f; }
        __syncthreads();
        if (tid < 64 && e[tid * 2 + 1] != 0) atomicAdd(&nz, 1);
        __syncthreads();
        if (tid == 0) g_idx_is64 = (nz == 0) ? 1 : 0;
    }
}

// ---------------- kernel 2: scatter (fp16 gather, fp32 RED) ----------
#define EB 8                    // edges per warp-iteration
#define SC_BLOCKS 592           // 4 per SM

__global__ void __launch_bounds__(256, 4)
scatter_kernel(const void* __restrict__ edge_index) {
    const int wid = threadIdx.x >> 5;
    const int lane = threadIdx.x & 31;
    const int wglob = blockIdx.x * 8 + wid;
    const int NW = SC_BLOCKS * 8;
    const bool is64 = (g_idx_is64 != 0);

#pragma unroll 1
    for (int it = 0; ; it++) {
        int e0 = (wglob + it * NW) * EB;
        if (e0 >= N_EDGES) break;
        int s[EB], d[EB];
        if (is64) {
            const long long* e = (const long long*)edge_index;
#pragma unroll
            for (int j = 0; j < EB; j++) {
                s[j] = (int)e[e0 + j];
                d[j] = (int)e[N_EDGES + e0 + j];
            }
        } else {
            const int* e = (const int*)edge_index;
            int4 sv0 = *(const int4*)(e + e0);
            int4 sv1 = *(const int4*)(e + e0 + 4);
            int4 dv0 = *(const int4*)(e + N_EDGES + e0);
            int4 dv1 = *(const int4*)(e + N_EDGES + e0 + 4);
            s[0] = sv0.x; s[1] = sv0.y; s[2] = sv0.z; s[3] = sv0.w;
            s[4] = sv1.x; s[5] = sv1.y; s[6] = sv1.z; s[7] = sv1.w;
            d[0] = dv0.x; d[1] = dv0.y; d[2] = dv0.z; d[3] = dv0.w;
            d[4] = dv1.x; d[5] = dv1.y; d[6] = dv1.z; d[7] = dv1.w;
        }
        int cnt = N_EDGES - e0; if (cnt > EB) cnt = EB;
        uint2 hv[EB];
#pragma unroll
        for (int j = 0; j < EB; j++) {
            bool ok = (j < cnt) && ((unsigned)s[j] < N_NODES);
            hv[j] = ok ? *((const uint2*)(g_x16 + (size_t)s[j] * D) + lane)
                       : make_uint2(0u, 0u);
        }
#pragma unroll
        for (int j = 0; j < EB; j++) {
            if ((j < cnt) && ((unsigned)s[j] < N_NODES) && ((unsigned)d[j] < N_NODES)) {
                float2 f0 = __half22float2(*(__half2*)&hv[j].x);
                float2 f1 = __half22float2(*(__half2*)&hv[j].y);
                red_add_v4(g_aggr + (size_t)d[j] * D + lane * 4,
                           make_float4(f0.x, f0.y, f1.x, f1.y));
            }
        }
    }
}

// ---------------- kernel 3: K=256 GEMM + bias + BN stats ------------------
// half 0: fp16 x16 @ fp16 W_root (single term)
// half 1: fp32 aggr split hi/lo @ fp16 W_rel (two terms)
__global__ void __launch_bounds__(256, 2)
gemmAB_kernel(const float* __restrict__ b_rel) {
    extern __shared__ char smem[];
    const uint32_t sb = smem_u32(smem);
    const int tid = threadIdx.x;
    const int w = tid >> 5;
    const int lid = tid & 31;
    const int m0 = blockIdx.x * 128;

    if (tid < 128) {
        ((float*)(smem + SM_BIAS))[tid] = b_rel[tid];
        ((float*)(smem + SM_SSUM))[tid] = 0.f;
        ((float*)(smem + SM_SSQ))[tid]  = 0.f;
    }

    float acc[16][4];
#pragma unroll
    for (int q = 0; q < 16; q++)
#pragma unroll
        for (int c = 0; c < 4; c++) acc[q][c] = 0.f;

    const int r = lid >> 2;
    const int cq = (lid & 3) * 2;
    const int m = m0 + w * 16 + r;
    const bool v0 = m < N_NODES;
    const bool v1 = (m + 8) < N_NODES;
    const float2 fz = make_float2(0.f, 0.f);

#pragma unroll 1
    for (int half = 0; half < 2; half++) {
        // fill B smem with fp16 W_root (half 0) or W_rel (half 1)
#pragma unroll
        for (int i = 0; i < 8; i++) {
            int ch = tid + i * 256;
            int row = ch >> 4, c16 = ch & 15;
            size_t gsrc = (size_t)((half * 128 + row) * 128 + c16 * 8) * 2;
            *(uint4*)(smem + B_HI + row * 272 + c16 * 16) =
                *(const uint4*)((const char*)gW_h + gsrc);
        }
        __syncthreads();

        if (half == 0) {
            const __half* ph0 = g_x16 + (size_t)m * D + cq;
            const __half* ph1 = g_x16 + (size_t)(m + 8) * D + cq;
#pragma unroll
            for (int s = 0; s < 8; s++) {
                const int ko = s * 16;
                uint32_t ah[4];
                ah[0] = v0 ? *(const uint32_t*)(ph0 + ko)     : 0u;
                ah[1] = v1 ? *(const uint32_t*)(ph1 + ko)     : 0u;
                ah[2] = v0 ? *(const uint32_t*)(ph0 + ko + 8) : 0u;
                ah[3] = v1 ? *(const uint32_t*)(ph1 + ko + 8) : 0u;
                const uint32_t rowa = sb + (uint32_t)((s * 16 + (lid & 15)) * 272
                                                      + (lid >> 4) * 16);
#pragma unroll
                for (int q8 = 0; q8 < 8; q8++) {
                    uint32_t bh[4];
                    ldsm_x4_t(bh[0], bh[1], bh[2], bh[3],
                              rowa + (uint32_t)(q8 * 32) + B_HI);
                    mma_f16(acc[q8 * 2],     ah, bh);
                    mma_f16(acc[q8 * 2 + 1], ah, bh + 2);
                }
            }
        } else {
            const float* pr0 = g_aggr + (size_t)m * D + cq;
            const float* pr1 = g_aggr + (size_t)(m + 8) * D + cq;
#pragma unroll
            for (int s = 0; s < 8; s++) {
                const int ko = s * 16;
                float2 x00 = v0 ? *(const float2*)(pr0 + ko) : fz;
                float2 x10 = v1 ? *(const float2*)(pr1 + ko) : fz;
                float2 x01 = v0 ? *(const float2*)(pr0 + ko + 8) : fz;
                float2 x11 = v1 ? *(const float2*)(pr1 + ko + 8) : fz;
                uint32_t ah[4], al[4];
                split_h(x00, ah[0], al[0]);
                split_h(x10, ah[1], al[1]);
                split_h(x01, ah[2], al[2]);
                split_h(x11, ah[3], al[3]);
                const uint32_t rowa = sb + (uint32_t)((s * 16 + (lid & 15)) * 272
                                                      + (lid >> 4) * 16);
#pragma unroll
                for (int q8 = 0; q8 < 8; q8++) {
                    uint32_t bh[4];
                    ldsm_x4_t(bh[0], bh[1], bh[2], bh[3],
                              rowa + (uint32_t)(q8 * 32) + B_HI);
                    float* c0 = acc[q8 * 2];
                    float* c1 = acc[q8 * 2 + 1];
                    mma_f16(c0, ah, bh);
                    mma_f16(c0, al, bh);
                    mma_f16(c1, ah, bh + 2);
                    mma_f16(c1, al, bh + 2);
                }
            }
        }
        __syncthreads();
    }

    // ---- epilogue: bias + direct store + BN stats (shuffle-reduced) ----
    const float* bs = (const float*)(smem + SM_BIAS);
    float* ssum = (float*)(smem + SM_SSUM);
    float* ssq  = (float*)(smem + SM_SSQ);
#pragma unroll
    for (int q = 0; q < 16; q++) {
        int n = q * 8 + cq;
        float b0 = bs[n], b1 = bs[n + 1];
        float s0 = 0.f, s1 = 0.f, q0 = 0.f, q1 = 0.f;
        if (v0) {
            float2 o = make_float2(acc[q][0] + b0, acc[q][1] + b1);
            *(float2*)(g_h + (size_t)m * D + n) = o;
            s0 += o.x; s1 += o.y;
            q0 += o.x * o.x; q1 += o.y * o.y;
        }
        if (v1) {
            float2 o = make_float2(acc[q][2] + b0, acc[q][3] + b1);
            *(float2*)(g_h + (size_t)(m + 8) * D + n) = o;
            s0 += o.x; s1 += o.y;
            q0 += o.x * o.x; q1 += o.y * o.y;
        }
#pragma unroll
        for (int mk = 4; mk <= 16; mk <<= 1) {
            s0 += __shfl_xor_sync(0xffffffffu, s0, mk);
            s1 += __shfl_xor_sync(0xffffffffu, s1, mk);
            q0 += __shfl_xor_sync(0xffffffffu, q0, mk);
            q1 += __shfl_xor_sync(0xffffffffu, q1, mk);
        }
        if ((lid >> 2) == 0) {
            atomicAdd(&ssum[n],     s0);
            atomicAdd(&ssum[n + 1], s1);
            atomicAdd(&ssq[n],      q0);
            atomicAdd(&ssq[n + 1],  q1);
        }
    }
    __syncthreads();
    if (tid < 128) {
        atomicAdd(&g_sum[tid],   ssum[tid]);
        atomicAdd(&g_sumsq[tid], ssq[tid]);
    }
}

// ---------------- fused finalize + normalize + ReLU ----------------
__global__ void norm_kernel(const float* __restrict__ gamma,
                            const float* __restrict__ beta,
                            float* __restrict__ out) {
    __shared__ float ssc[D], ssh[D];
    int t = threadIdx.x;
    if (t < D) {
        float inv_n = 1.0f / (float)N_NODES;
        float mean = g_sum[t] * inv_n;
        float var = g_sumsq[t] * inv_n - mean * mean;
        float sc = gamma[t] * rsqrtf(var + EPS);
        ssc[t] = sc;
        ssh[t] = beta[t] - mean * sc;
    }
    __syncthreads();
    int idx = blockIdx.x * blockDim.x + t;
    const int n4 = (N_NODES * D) / 4;
    if (idx >= n4) return;
    int c4 = (idx & (D / 4 - 1)) * 4;
    float4 h = ((const float4*)g_h)[idx];
    float4 o;
    o.x = fmaxf(h.x * ssc[c4 + 0] + ssh[c4 + 0], 0.f);
    o.y = fmaxf(h.y * ssc[c4 + 1] + ssh[c4 + 1], 0.f);
    o.z = fmaxf(h.z * ssc[c4 + 2] + ssh[c4 + 2], 0.f);
    o.w = fmaxf(h.w * ssc[c4 + 3] + ssh[c4 + 3], 0.f);
    ((float4*)out)[idx] = o;
}

// ---------------- launch ----------------
extern "C" void kernel_launch(void* const* d_in, const int* in_sizes, int n_in,
                              void* d_out, int out_size) {
    const float* x      = (const float*)d_in[0];
    const void*  eidx   = d_in[1];
    const float* W_root = (const float*)d_in[2];
    const float* W_rel  = (const float*)d_in[3];
    const float* b_rel  = (const float*)d_in[4];
    const float* gamma  = (const float*)d_in[5];
    const float* beta   = (const float*)d_in[6];
    float*       out    = (float*)d_out;

    cudaFuncSetAttribute(gemmAB_kernel,
                         cudaFuncAttributeMaxDynamicSharedMemorySize, SMEMSZ);

    const int n8 = (N_NODES * D) / 8;
    prologue_kernel<<<(n8 + 255) / 256, 256>>>(x, W_root, W_rel, (const int*)eidx);

    scatter_kernel<<<SC_BLOCKS, 256>>>(eidx);

    gemmAB_kernel<<<(N_NODES + 127) / 128, 256, SMEMSZ>>>(b_rel);

    const int n4 = (N_NODES * D) / 4;
    norm_kernel<<<(n4 + 255) / 256, 256>>>(gamma, beta, out);
}

// round 13
// speedup vs baseline: 1.0797x; 1.0144x over previous
#include <cuda_runtime.h>
#include <cuda_fp16.h>
#include <cstdint>

#define N_NODES 100000
#define N_EDGES 1600000
#define D 128
#define EPS 1e-5f
#define NSCAN 391              // ceil(100000/256)

// ---------------- scratch ----------------
__device__ float g_aggr[(size_t)N_NODES * D];
__device__ float g_h[(size_t)N_NODES * D];
__device__ __half g_x16[(size_t)N_NODES * D];
__device__ float g_sum[D];
__device__ float g_sumsq[D];
__device__ __half gW_h[256 * 128];   // rows 0-127 W_root, 128-255 W_rel
__device__ int g_deg[N_NODES];
__device__ int g_off[N_NODES + 1];
__device__ int g_fill[N_NODES];
__device__ int g_part[NSCAN];
__device__ int g_partoff[NSCAN];
__device__ int g_perm[N_EDGES];

// ---------------- helpers ----------------
__device__ __forceinline__ uint32_t smem_u32(const void* p) {
    uint32_t a;
    asm("{ .reg .u64 t; cvta.to.shared.u64 t, %1; cvt.u32.u64 %0, t; }"
        : "=r"(a) : "l"(p));
    return a;
}
__device__ __forceinline__ void ldsm_x4_t(uint32_t& r0, uint32_t& r1,
                                          uint32_t& r2, uint32_t& r3, uint32_t a) {
    asm volatile("ldmatrix.sync.aligned.m8n8.x4.trans.shared.b16 {%0,%1,%2,%3}, [%4];"
                 : "=r"(r0), "=r"(r1), "=r"(r2), "=r"(r3) : "r"(a));
}
__device__ __forceinline__ void mma_f16(float* c, const uint32_t* a, const uint32_t* b) {
    asm volatile("mma.sync.aligned.m16n8k16.row.col.f32.f16.f16.f32 "
                 "{%0,%1,%2,%3}, {%4,%5,%6,%7}, {%8,%9}, {%0,%1,%2,%3};"
                 : "+f"(c[0]), "+f"(c[1]), "+f"(c[2]), "+f"(c[3])
                 : "r"(a[0]), "r"(a[1]), "r"(a[2]), "r"(a[3]),
                   "r"(b[0]), "r"(b[1]));
}
__device__ __forceinline__ void split_h(float2 v, uint32_t& hi, uint32_t& lo) {
    __half h0 = __float2half_rn(v.x);
    __half h1 = __float2half_rn(v.y);
    __half2 hp = __halves2half2(h0, h1);
    __half2 lp = __halves2half2(__float2half_rn(v.x - __half2float(h0)),
                                __float2half_rn(v.y - __half2float(h1)));
    hi = *(uint32_t*)&hp;
    lo = *(uint32_t*)&lp;
}
// int64 detection: odd int32 words all-zero for int64 data in [0, 2^31)
__device__ __forceinline__ bool probe64(const void* e) {
    const int* p = (const int*)e;
    int acc = p[1] | p[3] | p[5] | p[7] | p[9] | p[11] | p[13] | p[15];
    return acc == 0;
}

// smem layout for GEMM
#define B_HI   0             // 128 rows * 272 B
#define SM_BIAS 34816
#define SM_SSUM 35328
#define SM_SSQ  35840
#define SMEMSZ  36352

// ---------------- kernel 1: prologue (x16 conv, wconv, zero deg+stats) ----
__global__ void prologue_kernel(const float* __restrict__ x,
                                const float* __restrict__ W_root,
                                const float* __restrict__ W_rel) {
    const int tid = threadIdx.x;
    const int idx = blockIdx.x * 256 + tid;
    const int n8 = (N_NODES * D) / 8;

    if (idx < n8) {
        const float4* src = (const float4*)x + idx * 2;
        float4 a = src[0], b = src[1];
        __half2 h0 = __halves2half2(__float2half_rn(a.x), __float2half_rn(a.y));
        __half2 h1 = __halves2half2(__float2half_rn(a.z), __float2half_rn(a.w));
        __half2 h2 = __halves2half2(__float2half_rn(b.x), __float2half_rn(b.y));
        __half2 h3 = __halves2half2(__float2half_rn(b.z), __float2half_rn(b.w));
        ((uint4*)g_x16)[idx] = make_uint4(*(uint32_t*)&h0, *(uint32_t*)&h1,
                                          *(uint32_t*)&h2, *(uint32_t*)&h3);
    }
    if (idx < 25000)
        ((int4*)g_deg)[idx] = make_int4(0, 0, 0, 0);

    if (idx < 8192) {
#pragma unroll
        for (int p = idx; p < 16384; p += 8192) {
            int k = p >> 6;
            int n2 = (p & 63) * 2;
            const float* W = (k < 128) ? (W_root + k * 128 + n2)
                                       : (W_rel + (k - 128) * 128 + n2);
            float2 v = *(const float2*)W;
            __half2 h = __halves2half2(__float2half_rn(v.x), __float2half_rn(v.y));
            *(uint32_t*)((char*)gW_h + (size_t)(k * 128 + n2) * 2) = *(uint32_t*)&h;
        }
    }
    if (blockIdx.x == 0 && tid < D) { g_sum[tid] = 0.f; g_sumsq[tid] = 0.f; }
}

// ---------------- kernel 2: degree histogram ----------------
__global__ void hist_kernel(const void* __restrict__ eidx) {
    const bool is64 = probe64(eidx);
    int base = (blockIdx.x * 256 + threadIdx.x) * 4;
    if (base >= N_EDGES) return;
    int d[4];
    if (is64) {
        const long long* e = (const long long*)eidx + N_EDGES + base;
        d[0] = (int)e[0]; d[1] = (int)e[1]; d[2] = (int)e[2]; d[3] = (int)e[3];
    } else {
        int4 v = *(const int4*)((const int*)eidx + N_EDGES + base);
        d[0] = v.x; d[1] = v.y; d[2] = v.z; d[3] = v.w;
    }
#pragma unroll
    for (int j = 0; j < 4; j++)
        if (base + j < N_EDGES && (unsigned)d[j] < N_NODES)
            atomicAdd(&g_deg[d[j]], 1);
}

// ---------------- kernel 3a/3b/3c: prefix scan of degrees ----------------
__global__ void scanA_kernel() {
    __shared__ int s[256];
    int i = blockIdx.x * 256 + threadIdx.x;
    s[threadIdx.x] = (i < N_NODES) ? g_deg[i] : 0;
    __syncthreads();
#pragma unroll
    for (int off = 128; off > 0; off >>= 1) {
        if (threadIdx.x < off) s[threadIdx.x] += s[threadIdx.x + off];
        __syncthreads();
    }
    if (threadIdx.x == 0) g_part[blockIdx.x] = s[0];
}

__global__ void scanB_kernel() {
    __shared__ int s[NSCAN];
    int t = threadIdx.x;
    if (t < NSCAN) s[t] = g_part[t];
    __syncthreads();
    if (t == 0) {
        int run = 0;
        for (int i = 0; i < NSCAN; i++) { int tmp = s[i]; s[i] = run; run += tmp; }
        g_off[N_NODES] = run;
    }
    __syncthreads();
    if (t < NSCAN) g_partoff[t] = s[t];
}

__global__ void scanC_kernel() {
    __shared__ int s[256];
    int t = threadIdx.x;
    int i = blockIdx.x * 256 + t;
    int v = (i < N_NODES) ? g_deg[i] : 0;
    s[t] = v;
    __syncthreads();
#pragma unroll
    for (int off = 1; off < 256; off <<= 1) {
        int add = (t >= off) ? s[t - off] : 0;
        __syncthreads();
        s[t] += add;
        __syncthreads();
    }
    if (i < N_NODES) {
        int excl = s[t] - v + g_partoff[blockIdx.x];
        g_off[i] = excl;
        g_fill[i] = excl;
    }
}

// ---------------- kernel 4: permute src ids into CSR slots ----------------
__global__ void permute_kernel(const void* __restrict__ eidx) {
    const bool is64 = probe64(eidx);
    int base = (blockIdx.x * 256 + threadIdx.x) * 4;
    if (base >= N_EDGES) return;
    int s[4], d[4];
    if (is64) {
        const long long* es = (const long long*)eidx + base;
        const long long* ed = (const long long*)eidx + N_EDGES + base;
        s[0] = (int)es[0]; s[1] = (int)es[1]; s[2] = (int)es[2]; s[3] = (int)es[3];
        d[0] = (int)ed[0]; d[1] = (int)ed[1]; d[2] = (int)ed[2]; d[3] = (int)ed[3];
    } else {
        int4 sv = *(const int4*)((const int*)eidx + base);
        int4 dv = *(const int4*)((const int*)eidx + N_EDGES + base);
        s[0] = sv.x; s[1] = sv.y; s[2] = sv.z; s[3] = sv.w;
        d[0] = dv.x; d[1] = dv.y; d[2] = dv.z; d[3] = dv.w;
    }
#pragma unroll
    for (int j = 0; j < 4; j++) {
        if (base + j < N_EDGES && (unsigned)d[j] < N_NODES) {
            int pos = atomicAdd(&g_fill[d[j]], 1);
            g_perm[pos] = ((unsigned)s[j] < N_NODES) ? s[j] : 0;
        }
    }
}

// ---------------- kernel 5: aggregate (warp per node, gather + sum) -------
__global__ void __launch_bounds__(256, 4)
aggregate_kernel() {
    int warp = blockIdx.x * 8 + (threadIdx.x >> 5);
    if (warp >= N_NODES) return;
    int lane = threadIdx.x & 31;
    int start = g_off[warp];
    int end = g_off[warp + 1];

    float4 acc = make_float4(0.f, 0.f, 0.f, 0.f);
    int j = start;
#pragma unroll 1
    for (; j + 4 <= end; j += 4) {
        int s0 = g_perm[j], s1 = g_perm[j + 1];
        int s2 = g_perm[j + 2], s3 = g_perm[j + 3];
        uint2 h0 = *((const uint2*)(g_x16 + (size_t)s0 * D) + lane);
        uint2 h1 = *((const uint2*)(g_x16 + (size_t)s1 * D) + lane);
        uint2 h2 = *((const uint2*)(g_x16 + (size_t)s2 * D) + lane);
        uint2 h3 = *((const uint2*)(g_x16 + (size_t)s3 * D) + lane);
#pragma unroll
        for (int q = 0; q < 4; q++) {
            uint2 hh = (q == 0) ? h0 : (q == 1) ? h1 : (q == 2) ? h2 : h3;
            float2 f0 = __half22float2(*(__half2*)&hh.x);
            float2 f1 = __half22float2(*(__half2*)&hh.y);
            acc.x += f0.x; acc.y += f0.y; acc.z += f1.x; acc.w += f1.y;
        }
    }
#pragma unroll 1
    for (; j < end; j++) {
        int s0 = g_perm[j];
        uint2 hh = *((const uint2*)(g_x16 + (size_t)s0 * D) + lane);
        float2 f0 = __half22float2(*(__half2*)&hh.x);
        float2 f1 = __half22float2(*(__half2*)&hh.y);
        acc.x += f0.x; acc.y += f0.y; acc.z += f1.x; acc.w += f1.y;
    }
    *((float4*)(g_aggr + (size_t)warp * D) + lane) = acc;
}

// ---------------- kernel 6: K=256 GEMM + bias + BN stats ------------------
__global__ void __launch_bounds__(256, 2)
gemmAB_kernel(const float* __restrict__ b_rel) {
    extern __shared__ char smem[];
    const uint32_t sb = smem_u32(smem);
    const int tid = threadIdx.x;
    const int w = tid >> 5;
    const int lid = tid & 31;
    const int m0 = blockIdx.x * 128;

    if (tid < 128) {
        ((float*)(smem + SM_BIAS))[tid] = b_rel[tid];
        ((float*)(smem + SM_SSUM))[tid] = 0.f;
        ((float*)(smem + SM_SSQ))[tid]  = 0.f;
    }

    float acc[16][4];
#pragma unroll
    for (int q = 0; q < 16; q++)
#pragma unroll
        for (int c = 0; c < 4; c++) acc[q][c] = 0.f;

    const int r = lid >> 2;
    const int cq = (lid & 3) * 2;
    const int m = m0 + w * 16 + r;
    const bool v0 = m < N_NODES;
    const bool v1 = (m + 8) < N_NODES;
    const float2 fz = make_float2(0.f, 0.f);

#pragma unroll 1
    for (int half = 0; half < 2; half++) {
#pragma unroll
        for (int i = 0; i < 8; i++) {
            int ch = tid + i * 256;
            int row = ch >> 4, c16 = ch & 15;
            size_t gsrc = (size_t)((half * 128 + row) * 128 + c16 * 8) * 2;
            *(uint4*)(smem + B_HI + row * 272 + c16 * 16) =
                *(const uint4*)((const char*)gW_h + gsrc);
        }
        __syncthreads();

        if (half == 0) {
            const __half* ph0 = g_x16 + (size_t)m * D + cq;
            const __half* ph1 = g_x16 + (size_t)(m + 8) * D + cq;
#pragma unroll
            for (int s = 0; s < 8; s++) {
                const int ko = s * 16;
                uint32_t ah[4];
                ah[0] = v0 ? *(const uint32_t*)(ph0 + ko)     : 0u;
                ah[1] = v1 ? *(const uint32_t*)(ph1 + ko)     : 0u;
                ah[2] = v0 ? *(const uint32_t*)(ph0 + ko + 8) : 0u;
                ah[3] = v1 ? *(const uint32_t*)(ph1 + ko + 8) : 0u;
                const uint32_t rowa = sb + (uint32_t)((s * 16 + (lid & 15)) * 272
                                                      + (lid >> 4) * 16);
#pragma unroll
                for (int q8 = 0; q8 < 8; q8++) {
                    uint32_t bh[4];
                    ldsm_x4_t(bh[0], bh[1], bh[2], bh[3],
                              rowa + (uint32_t)(q8 * 32) + B_HI);
                    mma_f16(acc[q8 * 2],     ah, bh);
                    mma_f16(acc[q8 * 2 + 1], ah, bh + 2);
                }
            }
        } else {
            const float* pr0 = g_aggr + (size_t)m * D + cq;
            const float* pr1 = g_aggr + (size_t)(m + 8) * D + cq;
#pragma unroll
            for (int s = 0; s < 8; s++) {
                const int ko = s * 16;
                float2 x00 = v0 ? *(const float2*)(pr0 + ko) : fz;
                float2 x10 = v1 ? *(const float2*)(pr1 + ko) : fz;
                float2 x01 = v0 ? *(const float2*)(pr0 + ko + 8) : fz;
                float2 x11 = v1 ? *(const float2*)(pr1 + ko + 8) : fz;
                uint32_t ah[4], al[4];
                split_h(x00, ah[0], al[0]);
                split_h(x10, ah[1], al[1]);
                split_h(x01, ah[2], al[2]);
                split_h(x11, ah[3], al[3]);
                const uint32_t rowa = sb + (uint32_t)((s * 16 + (lid & 15)) * 272
                                                      + (lid >> 4) * 16);
#pragma unroll
                for (int q8 = 0; q8 < 8; q8++) {
                    uint32_t bh[4];
                    ldsm_x4_t(bh[0], bh[1], bh[2], bh[3],
                              rowa + (uint32_t)(q8 * 32) + B_HI);
                    float* c0 = acc[q8 * 2];
                    float* c1 = acc[q8 * 2 + 1];
                    mma_f16(c0, ah, bh);
                    mma_f16(c0, al, bh);
                    mma_f16(c1, ah, bh + 2);
                    mma_f16(c1, al, bh + 2);
                }
            }
        }
        __syncthreads();
    }

    // ---- epilogue: bias + direct store + BN stats (shuffle-reduced) ----
    const float* bs = (const float*)(smem + SM_BIAS);
    float* ssum = (float*)(smem + SM_SSUM);
    float* ssq  = (float*)(smem + SM_SSQ);
#pragma unroll
    for (int q = 0; q < 16; q++) {
        int n = q * 8 + cq;
        float b0 = bs[n], b1 = bs[n + 1];
        float s0 = 0.f, s1 = 0.f, q0 = 0.f, q1 = 0.f;
        if (v0) {
            float2 o = make_float2(acc[q][0] + b0, acc[q][1] + b1);
            *(float2*)(g_h + (size_t)m * D + n) = o;
            s0 += o.x; s1 += o.y;
            q0 += o.x * o.x; q1 += o.y * o.y;
        }
        if (v1) {
            float2 o = make_float2(acc[q][2] + b0, acc[q][3] + b1);
            *(float2*)(g_h + (size_t)(m + 8) * D + n) = o;
            s0 += o.x; s1 += o.y;
            q0 += o.x * o.x; q1 += o.y * o.y;
        }
#pragma unroll
        for (int mk = 4; mk <= 16; mk <<= 1) {
            s0 += __shfl_xor_sync(0xffffffffu, s0, mk);
            s1 += __shfl_xor_sync(0xffffffffu, s1, mk);
            q0 += __shfl_xor_sync(0xffffffffu, q0, mk);
            q1 += __shfl_xor_sync(0xffffffffu, q1, mk);
        }
        if ((lid >> 2) == 0) {
            atomicAdd(&ssum[n],     s0);
            atomicAdd(&ssum[n + 1], s1);
            atomicAdd(&ssq[n],      q0);
            atomicAdd(&ssq[n + 1],  q1);
        }
    }
    __syncthreads();
    if (tid < 128) {
        atomicAdd(&g_sum[tid],   ssum[tid]);
        atomicAdd(&g_sumsq[tid], ssq[tid]);
    }
}

// ---------------- fused finalize + normalize + ReLU ----------------
__global__ void norm_kernel(const float* __restrict__ gamma,
                            const float* __restrict__ beta,
                            float* __restrict__ out) {
    __shared__ float ssc[D], ssh[D];
    int t = threadIdx.x;
    if (t < D) {
        float inv_n = 1.0f / (float)N_NODES;
        float mean = g_sum[t] * inv_n;
        float var = g_sumsq[t] * inv_n - mean * mean;
        float sc = gamma[t] * rsqrtf(var + EPS);
        ssc[t] = sc;
        ssh[t] = beta[t] - mean * sc;
    }
    __syncthreads();
    int idx = blockIdx.x * blockDim.x + t;
    const int n4 = (N_NODES * D) / 4;
    if (idx >= n4) return;
    int c4 = (idx & (D / 4 - 1)) * 4;
    float4 h = ((const float4*)g_h)[idx];
    float4 o;
    o.x = fmaxf(h.x * ssc[c4 + 0] + ssh[c4 + 0], 0.f);
    o.y = fmaxf(h.y * ssc[c4 + 1] + ssh[c4 + 1], 0.f);
    o.z = fmaxf(h.z * ssc[c4 + 2] + ssh[c4 + 2], 0.f);
    o.w = fmaxf(h.w * ssc[c4 + 3] + ssh[c4 + 3], 0.f);
    ((float4*)out)[idx] = o;
}

// ---------------- launch ----------------
extern "C" void kernel_launch(void* const* d_in, const int* in_sizes, int n_in,
                              void* d_out, int out_size) {
    const float* x      = (const float*)d_in[0];
    const void*  eidx   = d_in[1];
    const float* W_root = (const float*)d_in[2];
    const float* W_rel  = (const float*)d_in[3];
    const float* b_rel  = (const float*)d_in[4];
    const float* gamma  = (const float*)d_in[5];
    const float* beta   = (const float*)d_in[6];
    float*       out    = (float*)d_out;

    cudaFuncSetAttribute(gemmAB_kernel,
                         cudaFuncAttributeMaxDynamicSharedMemorySize, SMEMSZ);

    const int n8 = (N_NODES * D) / 8;
    prologue_kernel<<<(n8 + 255) / 256, 256>>>(x, W_root, W_rel);

    const int eblk = (N_EDGES / 4 + 255) / 256;
    hist_kernel<<<eblk, 256>>>(eidx);

    scanA_kernel<<<NSCAN, 256>>>();
    scanB_kernel<<<1, 512>>>();
    scanC_kernel<<<NSCAN, 256>>>();

    permute_kernel<<<eblk, 256>>>(eidx);

    aggregate_kernel<<<(N_NODES + 7) / 8, 256>>>();

    gemmAB_kernel<<<(N_NODES + 127) / 128, 256, SMEMSZ>>>(b_rel);

    const int n4 = (N_NODES * D) / 4;
    norm_kernel<<<(n4 + 255) / 256, 256>>>(gamma, beta, out);
}

// round 14
// speedup vs baseline: 1.4109x; 1.3068x over previous
#include <cuda_runtime.h>
#include <cuda_fp16.h>
#include <cstdint>

#define N_NODES 100000
#define N_EDGES 1600000
#define D 128
#define EPS 1e-5f
#define NSCAN 391              // ceil(100000/256)

// ---------------- scratch ----------------
__device__ float g_aggr[(size_t)N_NODES * D];
__device__ float g_h[(size_t)N_NODES * D];
__device__ __half g_x16[(size_t)N_NODES * D];
__device__ float g_sum[D];
__device__ float g_sumsq[D];
__device__ __half gW_h[256 * 128];   // rows 0-127 W_root, 128-255 W_rel
__device__ int g_deg[N_NODES];
__device__ int g_off[N_NODES + 1];
__device__ int g_fill[N_NODES];
__device__ int g_part[NSCAN];
__device__ int g_partoff[NSCAN];
__device__ int g_perm[N_EDGES];

// ---------------- helpers ----------------
__device__ __forceinline__ uint32_t smem_u32(const void* p) {
    uint32_t a;
    asm("{ .reg .u64 t; cvta.to.shared.u64 t, %1; cvt.u32.u64 %0, t; }"
        : "=r"(a) : "l"(p));
    return a;
}
__device__ __forceinline__ void ldsm_x4_t(uint32_t& r0, uint32_t& r1,
                                          uint32_t& r2, uint32_t& r3, uint32_t a) {
    asm volatile("ldmatrix.sync.aligned.m8n8.x4.trans.shared.b16 {%0,%1,%2,%3}, [%4];"
                 : "=r"(r0), "=r"(r1), "=r"(r2), "=r"(r3) : "r"(a));
}
__device__ __forceinline__ void mma_f16(float* c, const uint32_t* a, const uint32_t* b) {
    asm volatile("mma.sync.aligned.m16n8k16.row.col.f32.f16.f16.f32 "
                 "{%0,%1,%2,%3}, {%4,%5,%6,%7}, {%8,%9}, {%0,%1,%2,%3};"
                 : "+f"(c[0]), "+f"(c[1]), "+f"(c[2]), "+f"(c[3])
                 : "r"(a[0]), "r"(a[1]), "r"(a[2]), "r"(a[3]),
                   "r"(b[0]), "r"(b[1]));
}
__device__ __forceinline__ void split_h(float2 v, uint32_t& hi, uint32_t& lo) {
    __half h0 = __float2half_rn(v.x);
    __half h1 = __float2half_rn(v.y);
    __half2 hp = __halves2half2(h0, h1);
    __half2 lp = __halves2half2(__float2half_rn(v.x - __half2float(h0)),
                                __float2half_rn(v.y - __half2float(h1)));
    hi = *(uint32_t*)&hp;
    lo = *(uint32_t*)&lp;
}
__device__ __forceinline__ bool probe64(const void* e) {
    const int* p = (const int*)e;
    int acc = p[1] | p[3] | p[5] | p[7] | p[9] | p[11] | p[13] | p[15];
    return acc == 0;
}

// smem layout for GEMM
#define B_HI   0             // 128 rows * 272 B
#define SM_BIAS 34816
#define SM_SSUM 35328
#define SM_SSQ  35840
#define SMEMSZ  36352

// ---------------- kernel 1: prologue (x16 conv, wconv, zero deg+stats) ----
__global__ void prologue_kernel(const float* __restrict__ x,
                                const float* __restrict__ W_root,
                                const float* __restrict__ W_rel) {
    const int tid = threadIdx.x;
    const int idx = blockIdx.x * 256 + tid;
    const int n8 = (N_NODES * D) / 8;

    if (idx < n8) {
        const float4* src = (const float4*)x + idx * 2;
        float4 a = src[0], b = src[1];
        __half2 h0 = __halves2half2(__float2half_rn(a.x), __float2half_rn(a.y));
        __half2 h1 = __halves2half2(__float2half_rn(a.z), __float2half_rn(a.w));
        __half2 h2 = __halves2half2(__float2half_rn(b.x), __float2half_rn(b.y));
        __half2 h3 = __halves2half2(__float2half_rn(b.z), __float2half_rn(b.w));
        ((uint4*)g_x16)[idx] = make_uint4(*(uint32_t*)&h0, *(uint32_t*)&h1,
                                          *(uint32_t*)&h2, *(uint32_t*)&h3);
    }
    if (idx < 25000)
        ((int4*)g_deg)[idx] = make_int4(0, 0, 0, 0);

    if (idx < 8192) {
#pragma unroll
        for (int p = idx; p < 16384; p += 8192) {
            int k = p >> 6;
            int n2 = (p & 63) * 2;
            const float* W = (k < 128) ? (W_root + k * 128 + n2)
                                       : (W_rel + (k - 128) * 128 + n2);
            float2 v = *(const float2*)W;
            __half2 h = __halves2half2(__float2half_rn(v.x), __float2half_rn(v.y));
            *(uint32_t*)((char*)gW_h + (size_t)(k * 128 + n2) * 2) = *(uint32_t*)&h;
        }
    }
    if (blockIdx.x == 0 && tid < D) { g_sum[tid] = 0.f; g_sumsq[tid] = 0.f; }
}

// ---------------- kernel 2: degree histogram ----------------
__global__ void hist_kernel(const void* __restrict__ eidx) {
    const bool is64 = probe64(eidx);
    int base = (blockIdx.x * 256 + threadIdx.x) * 4;
    if (base >= N_EDGES) return;
    int d[4];
    if (is64) {
        const long long* e = (const long long*)eidx + N_EDGES + base;
        d[0] = (int)e[0]; d[1] = (int)e[1]; d[2] = (int)e[2]; d[3] = (int)e[3];
    } else {
        int4 v = *(const int4*)((const int*)eidx + N_EDGES + base);
        d[0] = v.x; d[1] = v.y; d[2] = v.z; d[3] = v.w;
    }
#pragma unroll
    for (int j = 0; j < 4; j++)
        if (base + j < N_EDGES && (unsigned)d[j] < N_NODES)
            atomicAdd(&g_deg[d[j]], 1);
}

// ---------------- kernel 3a/3b/3c: prefix scan of degrees ----------------
__global__ void scanA_kernel() {
    __shared__ int s[256];
    int i = blockIdx.x * 256 + threadIdx.x;
    s[threadIdx.x] = (i < N_NODES) ? g_deg[i] : 0;
    __syncthreads();
#pragma unroll
    for (int off = 128; off > 0; off >>= 1) {
        if (threadIdx.x < off) s[threadIdx.x] += s[threadIdx.x + off];
        __syncthreads();
    }
    if (threadIdx.x == 0) g_part[blockIdx.x] = s[0];
}

// parallel Hillis-Steele scan over the 391 partials
__global__ void scanB_kernel() {
    __shared__ int s[512];
    int t = threadIdx.x;
    int orig = (t < NSCAN) ? g_part[t] : 0;
    s[t] = orig;
    __syncthreads();
#pragma unroll
    for (int off = 1; off < 512; off <<= 1) {
        int v = (t >= off) ? s[t - off] : 0;
        __syncthreads();
        s[t] += v;
        __syncthreads();
    }
    if (t < NSCAN) g_partoff[t] = s[t] - orig;    // exclusive
    if (t == NSCAN - 1) g_off[N_NODES] = s[t];
}

__global__ void scanC_kernel() {
    __shared__ int s[256];
    int t = threadIdx.x;
    int i = blockIdx.x * 256 + t;
    int v = (i < N_NODES) ? g_deg[i] : 0;
    s[t] = v;
    __syncthreads();
#pragma unroll
    for (int off = 1; off < 256; off <<= 1) {
        int add = (t >= off) ? s[t - off] : 0;
        __syncthreads();
        s[t] += add;
        __syncthreads();
    }
    if (i < N_NODES) {
        int excl = s[t] - v + g_partoff[blockIdx.x];
        g_off[i] = excl;
        g_fill[i] = excl;
    }
}

// ---------------- kernel 4: permute src ids into CSR slots ----------------
__global__ void permute_kernel(const void* __restrict__ eidx) {
    const bool is64 = probe64(eidx);
    int base = (blockIdx.x * 256 + threadIdx.x) * 4;
    if (base >= N_EDGES) return;
    int s[4], d[4];
    if (is64) {
        const long long* es = (const long long*)eidx + base;
        const long long* ed = (const long long*)eidx + N_EDGES + base;
        s[0] = (int)es[0]; s[1] = (int)es[1]; s[2] = (int)es[2]; s[3] = (int)es[3];
        d[0] = (int)ed[0]; d[1] = (int)ed[1]; d[2] = (int)ed[2]; d[3] = (int)ed[3];
    } else {
        int4 sv = *(const int4*)((const int*)eidx + base);
        int4 dv = *(const int4*)((const int*)eidx + N_EDGES + base);
        s[0] = sv.x; s[1] = sv.y; s[2] = sv.z; s[3] = sv.w;
        d[0] = dv.x; d[1] = dv.y; d[2] = dv.z; d[3] = dv.w;
    }
#pragma unroll
    for (int j = 0; j < 4; j++) {
        if (base + j < N_EDGES && (unsigned)d[j] < N_NODES) {
            int pos = atomicAdd(&g_fill[d[j]], 1);
            g_perm[pos] = ((unsigned)s[j] < N_NODES) ? s[j] : 0;
        }
    }
}

// ---------------- kernel 5: aggregate (warp per node, MLP-8 gathers) ------
__global__ void __launch_bounds__(256, 4)
aggregate_kernel() {
    int warp = blockIdx.x * 8 + (threadIdx.x >> 5);
    if (warp >= N_NODES) return;
    int lane = threadIdx.x & 31;
    int start = g_off[warp];
    int cnt = g_off[warp + 1] - start;

    float4 acc = make_float4(0.f, 0.f, 0.f, 0.f);
#pragma unroll 1
    for (int base = 0; base < cnt; base += 32) {
        int nrem = min(32, cnt - base);
        // one coalesced load brings up to 32 neighbor ids
        int my = (lane < nrem) ? g_perm[start + base + lane] : 0;
#pragma unroll 1
        for (int g = 0; g < nrem; g += 8) {
            int nb = min(8, nrem - g);
            uint2 h[8];
#pragma unroll
            for (int k = 0; k < 8; k++) {
                int sidx = __shfl_sync(0xffffffffu, my, g + k);
                h[k] = (k < nb)
                     ? *((const uint2*)(g_x16 + (size_t)sidx * D) + lane)
                     : make_uint2(0u, 0u);
            }
#pragma unroll
            for (int k = 0; k < 8; k++) {
                float2 f0 = __half22float2(*(__half2*)&h[k].x);
                float2 f1 = __half22float2(*(__half2*)&h[k].y);
                acc.x += f0.x; acc.y += f0.y; acc.z += f1.x; acc.w += f1.y;
            }
        }
    }
    *((float4*)(g_aggr + (size_t)warp * D) + lane) = acc;
}

// ---------------- kernel 6: K=256 GEMM + bias + BN stats ------------------
__global__ void __launch_bounds__(256, 2)
gemmAB_kernel(const float* __restrict__ b_rel) {
    extern __shared__ char smem[];
    const uint32_t sb = smem_u32(smem);
    const int tid = threadIdx.x;
    const int w = tid >> 5;
    const int lid = tid & 31;
    const int m0 = blockIdx.x * 128;

    if (tid < 128) {
        ((float*)(smem + SM_BIAS))[tid] = b_rel[tid];
        ((float*)(smem + SM_SSUM))[tid] = 0.f;
        ((float*)(smem + SM_SSQ))[tid]  = 0.f;
    }

    float acc[16][4];
#pragma unroll
    for (int q = 0; q < 16; q++)
#pragma unroll
        for (int c = 0; c < 4; c++) acc[q][c] = 0.f;

    const int r = lid >> 2;
    const int cq = (lid & 3) * 2;
    const int m = m0 + w * 16 + r;
    const bool v0 = m < N_NODES;
    const bool v1 = (m + 8) < N_NODES;
    const float2 fz = make_float2(0.f, 0.f);

#pragma unroll 1
    for (int half = 0; half < 2; half++) {
#pragma unroll
        for (int i = 0; i < 8; i++) {
            int ch = tid + i * 256;
            int row = ch >> 4, c16 = ch & 15;
            size_t gsrc = (size_t)((half * 128 + row) * 128 + c16 * 8) * 2;
            *(uint4*)(smem + B_HI + row * 272 + c16 * 16) =
                *(const uint4*)((const char*)gW_h + gsrc);
        }
        __syncthreads();

        if (half == 0) {
            const __half* ph0 = g_x16 + (size_t)m * D + cq;
            const __half* ph1 = g_x16 + (size_t)(m + 8) * D + cq;
#pragma unroll
            for (int s = 0; s < 8; s++) {
                const int ko = s * 16;
                uint32_t ah[4];
                ah[0] = v0 ? *(const uint32_t*)(ph0 + ko)     : 0u;
                ah[1] = v1 ? *(const uint32_t*)(ph1 + ko)     : 0u;
                ah[2] = v0 ? *(const uint32_t*)(ph0 + ko + 8) : 0u;
                ah[3] = v1 ? *(const uint32_t*)(ph1 + ko + 8) : 0u;
                const uint32_t rowa = sb + (uint32_t)((s * 16 + (lid & 15)) * 272
                                                      + (lid >> 4) * 16);
#pragma unroll
                for (int q8 = 0; q8 < 8; q8++) {
                    uint32_t bh[4];
                    ldsm_x4_t(bh[0], bh[1], bh[2], bh[3],
                              rowa + (uint32_t)(q8 * 32) + B_HI);
                    mma_f16(acc[q8 * 2],     ah, bh);
                    mma_f16(acc[q8 * 2 + 1], ah, bh + 2);
                }
            }
        } else {
            const float* pr0 = g_aggr + (size_t)m * D + cq;
            const float* pr1 = g_aggr + (size_t)(m + 8) * D + cq;
#pragma unroll
            for (int s = 0; s < 8; s++) {
                const int ko = s * 16;
                float2 x00 = v0 ? *(const float2*)(pr0 + ko) : fz;
                float2 x10 = v1 ? *(const float2*)(pr1 + ko) : fz;
                float2 x01 = v0 ? *(const float2*)(pr0 + ko + 8) : fz;
                float2 x11 = v1 ? *(const float2*)(pr1 + ko + 8) : fz;
                uint32_t ah[4], al[4];
                split_h(x00, ah[0], al[0]);
                split_h(x10, ah[1], al[1]);
                split_h(x01, ah[2], al[2]);
                split_h(x11, ah[3], al[3]);
                const uint32_t rowa = sb + (uint32_t)((s * 16 + (lid & 15)) * 272
                                                      + (lid >> 4) * 16);
#pragma unroll
                for (int q8 = 0; q8 < 8; q8++) {
                    uint32_t bh[4];
                    ldsm_x4_t(bh[0], bh[1], bh[2], bh[3],
                              rowa + (uint32_t)(q8 * 32) + B_HI);
                    float* c0 = acc[q8 * 2];
                    float* c1 = acc[q8 * 2 + 1];
                    mma_f16(c0, ah, bh);
                    mma_f16(c0, al, bh);
                    mma_f16(c1, ah, bh + 2);
                    mma_f16(c1, al, bh + 2);
                }
            }
        }
        __syncthreads();
    }

    // ---- epilogue: bias + direct store + BN stats (shuffle-reduced) ----
    const float* bs = (const float*)(smem + SM_BIAS);
    float* ssum = (float*)(smem + SM_SSUM);
    float* ssq  = (float*)(smem + SM_SSQ);
#pragma unroll
    for (int q = 0; q < 16; q++) {
        int n = q * 8 + cq;
        float b0 = bs[n], b1 = bs[n + 1];
        float s0 = 0.f, s1 = 0.f, q0 = 0.f, q1 = 0.f;
        if (v0) {
            float2 o = make_float2(acc[q][0] + b0, acc[q][1] + b1);
            *(float2*)(g_h + (size_t)m * D + n) = o;
            s0 += o.x; s1 += o.y;
            q0 += o.x * o.x; q1 += o.y * o.y;
        }
        if (v1) {
            float2 o = make_float2(acc[q][2] + b0, acc[q][3] + b1);
            *(float2*)(g_h + (size_t)(m + 8) * D + n) = o;
            s0 += o.x; s1 += o.y;
            q0 += o.x * o.x; q1 += o.y * o.y;
        }
#pragma unroll
        for (int mk = 4; mk <= 16; mk <<= 1) {
            s0 += __shfl_xor_sync(0xffffffffu, s0, mk);
            s1 += __shfl_xor_sync(0xffffffffu, s1, mk);
            q0 += __shfl_xor_sync(0xffffffffu, q0, mk);
            q1 += __shfl_xor_sync(0xffffffffu, q1, mk);
        }
        if ((lid >> 2) == 0) {
            atomicAdd(&ssum[n],     s0);
            atomicAdd(&ssum[n + 1], s1);
            atomicAdd(&ssq[n],      q0);
            atomicAdd(&ssq[n + 1],  q1);
        }
    }
    __syncthreads();
    if (tid < 128) {
        atomicAdd(&g_sum[tid],   ssum[tid]);
        atomicAdd(&g_sumsq[tid], ssq[tid]);
    }
}

// ---------------- fused finalize + normalize + ReLU ----------------
__global__ void norm_kernel(const float* __restrict__ gamma,
                            const float* __restrict__ beta,
                            float* __restrict__ out) {
    __shared__ float ssc[D], ssh[D];
    int t = threadIdx.x;
    if (t < D) {
        float inv_n = 1.0f / (float)N_NODES;
        float mean = g_sum[t] * inv_n;
        float var = g_sumsq[t] * inv_n - mean * mean;
        float sc = gamma[t] * rsqrtf(var + EPS);
        ssc[t] = sc;
        ssh[t] = beta[t] - mean * sc;
    }
    __syncthreads();
    int idx = blockIdx.x * blockDim.x + t;
    const int n4 = (N_NODES * D) / 4;
    if (idx >= n4) return;
    int c4 = (idx & (D / 4 - 1)) * 4;
    float4 h = ((const float4*)g_h)[idx];
    float4 o;
    o.x = fmaxf(h.x * ssc[c4 + 0] + ssh[c4 + 0], 0.f);
    o.y = fmaxf(h.y * ssc[c4 + 1] + ssh[c4 + 1], 0.f);
    o.z = fmaxf(h.z * ssc[c4 + 2] + ssh[c4 + 2], 0.f);
    o.w = fmaxf(h.w * ssc[c4 + 3] + ssh[c4 + 3], 0.f);
    ((float4*)out)[idx] = o;
}

// ---------------- launch ----------------
extern "C" void kernel_launch(void* const* d_in, const int* in_sizes, int n_in,
                              void* d_out, int out_size) {
    const float* x      = (const float*)d_in[0];
    const void*  eidx   = d_in[1];
    const float* W_root = (const float*)d_in[2];
    const float* W_rel  = (const float*)d_in[3];
    const float* b_rel  = (const float*)d_in[4];
    const float* gamma  = (const float*)d_in[5];
    const float* beta   = (const float*)d_in[6];
    float*       out    = (float*)d_out;

    cudaFuncSetAttribute(gemmAB_kernel,
                         cudaFuncAttributeMaxDynamicSharedMemorySize, SMEMSZ);

    const int n8 = (N_NODES * D) / 8;
    prologue_kernel<<<(n8 + 255) / 256, 256>>>(x, W_root, W_rel);

    const int eblk = (N_EDGES / 4 + 255) / 256;
    hist_kernel<<<eblk, 256>>>(eidx);

    scanA_kernel<<<NSCAN, 256>>>();
    scanB_kernel<<<1, 512>>>();
    scanC_kernel<<<NSCAN, 256>>>();

    permute_kernel<<<eblk, 256>>>(eidx);

    aggregate_kernel<<<(N_NODES + 7) / 8, 256>>>();

    gemmAB_kernel<<<(N_NODES + 127) / 128, 256, SMEMSZ>>>(b_rel);

    const int n4 = (N_NODES * D) / 4;
    norm_kernel<<<(n4 + 255) / 256, 256>>>(gamma, beta, out);
}

// round 15
// speedup vs baseline: 1.5086x; 1.0692x over previous
#include <cuda_runtime.h>
#include <cuda_fp16.h>
#include <cstdint>

#define N_NODES 100000
#define N_EDGES 1600000
#define D 128
#define EPS 1e-5f
#define NSCAN 391              // ceil(100000/256)

// ---------------- scratch ----------------
__device__ __half g_aggr16[(size_t)N_NODES * D];
__device__ float g_h[(size_t)N_NODES * D];
__device__ __half g_x16[(size_t)N_NODES * D];
__device__ float g_sum[D];
__device__ float g_sumsq[D];
__device__ __half gW_h[256 * 128];   // rows 0-127 W_root, 128-255 W_rel
__device__ int g_deg[N_NODES];
__device__ int g_off[N_NODES + 1];
__device__ int g_fill[N_NODES];
__device__ int g_part[NSCAN];
__device__ int g_perm[N_EDGES];

// ---------------- helpers ----------------
__device__ __forceinline__ uint32_t smem_u32(const void* p) {
    uint32_t a;
    asm("{ .reg .u64 t; cvta.to.shared.u64 t, %1; cvt.u32.u64 %0, t; }"
        : "=r"(a) : "l"(p));
    return a;
}
__device__ __forceinline__ void ldsm_x4_t(uint32_t& r0, uint32_t& r1,
                                          uint32_t& r2, uint32_t& r3, uint32_t a) {
    asm volatile("ldmatrix.sync.aligned.m8n8.x4.trans.shared.b16 {%0,%1,%2,%3}, [%4];"
                 : "=r"(r0), "=r"(r1), "=r"(r2), "=r"(r3) : "r"(a));
}
__device__ __forceinline__ void mma_f16(float* c, const uint32_t* a, const uint32_t* b) {
    asm volatile("mma.sync.aligned.m16n8k16.row.col.f32.f16.f16.f32 "
                 "{%0,%1,%2,%3}, {%4,%5,%6,%7}, {%8,%9}, {%0,%1,%2,%3};"
                 : "+f"(c[0]), "+f"(c[1]), "+f"(c[2]), "+f"(c[3])
                 : "r"(a[0]), "r"(a[1]), "r"(a[2]), "r"(a[3]),
                   "r"(b[0]), "r"(b[1]));
}
__device__ __forceinline__ bool probe64(const void* e) {
    const int* p = (const int*)e;
    int acc = p[1] | p[3] | p[5] | p[7] | p[9] | p[11] | p[13] | p[15];
    return acc == 0;
}

// smem layout for GEMM
#define B_HI   0             // 128 rows * 272 B
#define SM_BIAS 34816
#define SM_SSUM 35328
#define SM_SSQ  35840
#define SMEMSZ  36352

// ---------------- kernel 1: prologue (x16 conv, wconv, zero deg+stats) ----
__global__ void prologue_kernel(const float* __restrict__ x,
                                const float* __restrict__ W_root,
                                const float* __restrict__ W_rel) {
    const int tid = threadIdx.x;
    const int idx = blockIdx.x * 256 + tid;
    const int n8 = (N_NODES * D) / 8;

    if (idx < n8) {
        const float4* src = (const float4*)x + idx * 2;
        float4 a = src[0], b = src[1];
        __half2 h0 = __halves2half2(__float2half_rn(a.x), __float2half_rn(a.y));
        __half2 h1 = __halves2half2(__float2half_rn(a.z), __float2half_rn(a.w));
        __half2 h2 = __halves2half2(__float2half_rn(b.x), __float2half_rn(b.y));
        __half2 h3 = __halves2half2(__float2half_rn(b.z), __float2half_rn(b.w));
        ((uint4*)g_x16)[idx] = make_uint4(*(uint32_t*)&h0, *(uint32_t*)&h1,
                                          *(uint32_t*)&h2, *(uint32_t*)&h3);
    }
    if (idx < 25000)
        ((int4*)g_deg)[idx] = make_int4(0, 0, 0, 0);

    if (idx < 8192) {
#pragma unroll
        for (int p = idx; p < 16384; p += 8192) {
            int k = p >> 6;
            int n2 = (p & 63) * 2;
            const float* W = (k < 128) ? (W_root + k * 128 + n2)
                                       : (W_rel + (k - 128) * 128 + n2);
            float2 v = *(const float2*)W;
            __half2 h = __halves2half2(__float2half_rn(v.x), __float2half_rn(v.y));
            *(uint32_t*)((char*)gW_h + (size_t)(k * 128 + n2) * 2) = *(uint32_t*)&h;
        }
    }
    if (blockIdx.x == 0 && tid < D) { g_sum[tid] = 0.f; g_sumsq[tid] = 0.f; }
}

// ---------------- kernel 2: degree histogram ----------------
__global__ void hist_kernel(const void* __restrict__ eidx) {
    const bool is64 = probe64(eidx);
    int base = (blockIdx.x * 256 + threadIdx.x) * 4;
    if (base >= N_EDGES) return;
    int d[4];
    if (is64) {
        const long long* e = (const long long*)eidx + N_EDGES + base;
        d[0] = (int)e[0]; d[1] = (int)e[1]; d[2] = (int)e[2]; d[3] = (int)e[3];
    } else {
        int4 v = *(const int4*)((const int*)eidx + N_EDGES + base);
        d[0] = v.x; d[1] = v.y; d[2] = v.z; d[3] = v.w;
    }
#pragma unroll
    for (int j = 0; j < 4; j++)
        if (base + j < N_EDGES && (unsigned)d[j] < N_NODES)
            atomicAdd(&g_deg[d[j]], 1);
}

// ---------------- kernel 3a: per-block degree sums ----------------
__global__ void scanA_kernel() {
    __shared__ int s[256];
    int i = blockIdx.x * 256 + threadIdx.x;
    s[threadIdx.x] = (i < N_NODES) ? g_deg[i] : 0;
    __syncthreads();
#pragma unroll
    for (int off = 128; off > 0; off >>= 1) {
        if (threadIdx.x < off) s[threadIdx.x] += s[threadIdx.x + off];
        __syncthreads();
    }
    if (threadIdx.x == 0) g_part[blockIdx.x] = s[0];
}

// ---------------- kernel 3b: block scan + inline partial-prefix ----------
__global__ void scanC_kernel() {
    __shared__ int s[256];
    __shared__ int red[256];
    int t = threadIdx.x;
    int i = blockIdx.x * 256 + t;

    // sum of partials with index < blockIdx.x (each block computes its own)
    int p = 0;
    if (t < NSCAN && t < blockIdx.x) p = g_part[t];
    if (t + 256 < NSCAN && t + 256 < blockIdx.x) p += g_part[t + 256];
    red[t] = p;
    __syncthreads();
#pragma unroll
    for (int off = 128; off > 0; off >>= 1) {
        if (t < off) red[t] += red[t + off];
        __syncthreads();
    }
    const int blockoff = red[0];

    int v = (i < N_NODES) ? g_deg[i] : 0;
    s[t] = v;
    __syncthreads();
#pragma unroll
    for (int off = 1; off < 256; off <<= 1) {
        int add = (t >= off) ? s[t - off] : 0;
        __syncthreads();
        s[t] += add;
        __syncthreads();
    }
    if (i < N_NODES) {
        int excl = s[t] - v + blockoff;
        g_off[i] = excl;
        g_fill[i] = excl;
    }
    if (blockIdx.x == NSCAN - 1 && t == 255)
        g_off[N_NODES] = blockoff + s[255];
}

// ---------------- kernel 4: permute src ids into CSR slots ----------------
__global__ void permute_kernel(const void* __restrict__ eidx) {
    const bool is64 = probe64(eidx);
    int base = (blockIdx.x * 256 + threadIdx.x) * 4;
    if (base >= N_EDGES) return;
    int s[4], d[4];
    if (is64) {
        const long long* es = (const long long*)eidx + base;
        const long long* ed = (const long long*)eidx + N_EDGES + base;
        s[0] = (int)es[0]; s[1] = (int)es[1]; s[2] = (int)es[2]; s[3] = (int)es[3];
        d[0] = (int)ed[0]; d[1] = (int)ed[1]; d[2] = (int)ed[2]; d[3] = (int)ed[3];
    } else {
        int4 sv = *(const int4*)((const int*)eidx + base);
        int4 dv = *(const int4*)((const int*)eidx + N_EDGES + base);
        s[0] = sv.x; s[1] = sv.y; s[2] = sv.z; s[3] = sv.w;
        d[0] = dv.x; d[1] = dv.y; d[2] = dv.z; d[3] = dv.w;
    }
#pragma unroll
    for (int j = 0; j < 4; j++) {
        if (base + j < N_EDGES && (unsigned)d[j] < N_NODES) {
            int pos = atomicAdd(&g_fill[d[j]], 1);
            g_perm[pos] = ((unsigned)s[j] < N_NODES) ? s[j] : 0;
        }
    }
}

// ---------------- kernel 5: aggregate (warp per node, MLP-8 gathers) ------
__global__ void __launch_bounds__(256, 4)
aggregate_kernel() {
    int warp = blockIdx.x * 8 + (threadIdx.x >> 5);
    if (warp >= N_NODES) return;
    int lane = threadIdx.x & 31;
    int start = g_off[warp];
    int cnt = g_off[warp + 1] - start;

    float4 acc = make_float4(0.f, 0.f, 0.f, 0.f);
#pragma unroll 1
    for (int base = 0; base < cnt; base += 32) {
        int nrem = min(32, cnt - base);
        int my = (lane < nrem) ? g_perm[start + base + lane] : 0;
#pragma unroll 1
        for (int g = 0; g < nrem; g += 8) {
            int nb = min(8, nrem - g);
            uint2 h[8];
#pragma unroll
            for (int k = 0; k < 8; k++) {
                int sidx = __shfl_sync(0xffffffffu, my, g + k);
                h[k] = (k < nb)
                     ? *((const uint2*)(g_x16 + (size_t)sidx * D) + lane)
                     : make_uint2(0u, 0u);
            }
#pragma unroll
            for (int k = 0; k < 8; k++) {
                float2 f0 = __half22float2(*(__half2*)&h[k].x);
                float2 f1 = __half22float2(*(__half2*)&h[k].y);
                acc.x += f0.x; acc.y += f0.y; acc.z += f1.x; acc.w += f1.y;
            }
        }
    }
    __half2 o0 = __halves2half2(__float2half_rn(acc.x), __float2half_rn(acc.y));
    __half2 o1 = __halves2half2(__float2half_rn(acc.z), __float2half_rn(acc.w));
    *((uint2*)(g_aggr16 + (size_t)warp * D) + lane) =
        make_uint2(*(uint32_t*)&o0, *(uint32_t*)&o1);
}

// ---------------- kernel 6: K=256 fp16 GEMM + bias + BN stats -------------
// h = x16@W_root + aggr16@W_rel + b_rel   (both halves pure fp16 A)
__global__ void __launch_bounds__(256, 2)
gemmAB_kernel(const float* __restrict__ b_rel) {
    extern __shared__ char smem[];
    const uint32_t sb = smem_u32(smem);
    const int tid = threadIdx.x;
    const int w = tid >> 5;
    const int lid = tid & 31;
    const int m0 = blockIdx.x * 128;

    if (tid < 128) {
        ((float*)(smem + SM_BIAS))[tid] = b_rel[tid];
        ((float*)(smem + SM_SSUM))[tid] = 0.f;
        ((float*)(smem + SM_SSQ))[tid]  = 0.f;
    }

    float acc[16][4];
#pragma unroll
    for (int q = 0; q < 16; q++)
#pragma unroll
        for (int c = 0; c < 4; c++) acc[q][c] = 0.f;

    const int r = lid >> 2;
    const int cq = (lid & 3) * 2;
    const int m = m0 + w * 16 + r;
    const bool v0 = m < N_NODES;
    const bool v1 = (m + 8) < N_NODES;

#pragma unroll 1
    for (int half = 0; half < 2; half++) {
#pragma unroll
        for (int i = 0; i < 8; i++) {
            int ch = tid + i * 256;
            int row = ch >> 4, c16 = ch & 15;
            size_t gsrc = (size_t)((half * 128 + row) * 128 + c16 * 8) * 2;
            *(uint4*)(smem + B_HI + row * 272 + c16 * 16) =
                *(const uint4*)((const char*)gW_h + gsrc);
        }
        __syncthreads();

        const __half* ph0 = (half ? g_aggr16 : g_x16) + (size_t)m * D + cq;
        const __half* ph1 = (half ? g_aggr16 : g_x16) + (size_t)(m + 8) * D + cq;
#pragma unroll
        for (int s = 0; s < 8; s++) {
            const int ko = s * 16;
            uint32_t ah[4];
            ah[0] = v0 ? *(const uint32_t*)(ph0 + ko)     : 0u;
            ah[1] = v1 ? *(const uint32_t*)(ph1 + ko)     : 0u;
            ah[2] = v0 ? *(const uint32_t*)(ph0 + ko + 8) : 0u;
            ah[3] = v1 ? *(const uint32_t*)(ph1 + ko + 8) : 0u;
            const uint32_t rowa = sb + (uint32_t)((s * 16 + (lid & 15)) * 272
                                                  + (lid >> 4) * 16);
#pragma unroll
            for (int q8 = 0; q8 < 8; q8++) {
                uint32_t bh[4];
                ldsm_x4_t(bh[0], bh[1], bh[2], bh[3],
                          rowa + (uint32_t)(q8 * 32) + B_HI);
                mma_f16(acc[q8 * 2],     ah, bh);
                mma_f16(acc[q8 * 2 + 1], ah, bh + 2);
            }
        }
        __syncthreads();
    }

    // ---- epilogue: bias + direct store + BN stats (shuffle-reduced) ----
    const float* bs = (const float*)(smem + SM_BIAS);
    float* ssum = (float*)(smem + SM_SSUM);
    float* ssq  = (float*)(smem + SM_SSQ);
#pragma unroll
    for (int q = 0; q < 16; q++) {
        int n = q * 8 + cq;
        float b0 = bs[n], b1 = bs[n + 1];
        float s0 = 0.f, s1 = 0.f, q0 = 0.f, q1 = 0.f;
        if (v0) {
            float2 o = make_float2(acc[q][0] + b0, acc[q][1] + b1);
            *(float2*)(g_h + (size_t)m * D + n) = o;
            s0 += o.x; s1 += o.y;
            q0 += o.x * o.x; q1 += o.y * o.y;
        }
        if (v1) {
            float2 o = make_float2(acc[q][2] + b0, acc[q][3] + b1);
            *(float2*)(g_h + (size_t)(m + 8) * D + n) = o;
            s0 += o.x; s1 += o.y;
            q0 += o.x * o.x; q1 += o.y * o.y;
        }
#pragma unroll
        for (int mk = 4; mk <= 16; mk <<= 1) {
            s0 += __shfl_xor_sync(0xffffffffu, s0, mk);
            s1 += __shfl_xor_sync(0xffffffffu, s1, mk);
            q0 += __shfl_xor_sync(0xffffffffu, q0, mk);
            q1 += __shfl_xor_sync(0xffffffffu, q1, mk);
        }
        if ((lid >> 2) == 0) {
            atomicAdd(&ssum[n],     s0);
            atomicAdd(&ssum[n + 1], s1);
            atomicAdd(&ssq[n],      q0);
            atomicAdd(&ssq[n + 1],  q1);
        }
    }
    __syncthreads();
    if (tid < 128) {
        atomicAdd(&g_sum[tid],   ssum[tid]);
        atomicAdd(&g_sumsq[tid], ssq[tid]);
    }
}

// ---------------- fused finalize + normalize + ReLU ----------------
__global__ void norm_kernel(const float* __restrict__ gamma,
                            const float* __restrict__ beta,
                            float* __restrict__ out) {
    __shared__ float ssc[D], ssh[D];
    int t = threadIdx.x;
    if (t < D) {
        float inv_n = 1.0f / (float)N_NODES;
        float mean = g_sum[t] * inv_n;
        float var = g_sumsq[t] * inv_n - mean * mean;
        float sc = gamma[t] * rsqrtf(var + EPS);
        ssc[t] = sc;
        ssh[t] = beta[t] - mean * sc;
    }
    __syncthreads();
    int idx = blockIdx.x * blockDim.x + t;
    const int n4 = (N_NODES * D) / 4;
    if (idx >= n4) return;
    int c4 = (idx & (D / 4 - 1)) * 4;
    float4 h = ((const float4*)g_h)[idx];
    float4 o;
    o.x = fmaxf(h.x * ssc[c4 + 0] + ssh[c4 + 0], 0.f);
    o.y = fmaxf(h.y * ssc[c4 + 1] + ssh[c4 + 1], 0.f);
    o.z = fmaxf(h.z * ssc[c4 + 2] + ssh[c4 + 2], 0.f);
    o.w = fmaxf(h.w * ssc[c4 + 3] + ssh[c4 + 3], 0.f);
    ((float4*)out)[idx] = o;
}

// ---------------- launch ----------------
extern "C" void kernel_launch(void* const* d_in, const int* in_sizes, int n_in,
                              void* d_out, int out_size) {
    const float* x      = (const float*)d_in[0];
    const void*  eidx   = d_in[1];
    const float* W_root = (const float*)d_in[2];
    const float* W_rel  = (const float*)d_in[3];
    const float* b_rel  = (const float*)d_in[4];
    const float* gamma  = (const float*)d_in[5];
    const float* beta   = (const float*)d_in[6];
    float*       out    = (float*)d_out;

    cudaFuncSetAttribute(gemmAB_kernel,
                         cudaFuncAttributeMaxDynamicSharedMemorySize, SMEMSZ);

    const int n8 = (N_NODES * D) / 8;
    prologue_kernel<<<(n8 + 255) / 256, 256>>>(x, W_root, W_rel);

    const int eblk = (N_EDGES / 4 + 255) / 256;
    hist_kernel<<<eblk, 256>>>(eidx);

    scanA_kernel<<<NSCAN, 256>>>();
    scanC_kernel<<<NSCAN, 256>>>();

    permute_kernel<<<eblk, 256>>>(eidx);

    aggregate_kernel<<<(N_NODES + 7) / 8, 256>>>();

    gemmAB_kernel<<<(N_NODES + 127) / 128, 256, SMEMSZ>>>(b_rel);

    const int n4 = (N_NODES * D) / 4;
    norm_kernel<<<(n4 + 255) / 256, 256>>>(gamma, beta, out);
}

// round 16
// speedup vs baseline: 1.5301x; 1.0142x over previous
#include <cuda_runtime.h>
#include <cuda_fp16.h>
#include <cstdint>

#define N_NODES 100000
#define N_EDGES 1600000
#define D 128
#define EPS 1e-5f
#define NSCAN 391              // ceil(100000/256)

// ---------------- scratch ----------------
__device__ __half g_aggr16[(size_t)N_NODES * D];
__device__ __half g_h16[(size_t)N_NODES * D];
__device__ __half g_x16[(size_t)N_NODES * D];
__device__ float g_sum[D];
__device__ float g_sumsq[D];
__device__ __half gW_h[256 * 128];   // rows 0-127 W_root, 128-255 W_rel
__device__ int g_deg[N_NODES];
__device__ int g_off[N_NODES + 1];
__device__ int g_fill[N_NODES];
__device__ int g_part[NSCAN];
__device__ int g_perm[N_EDGES];

// ---------------- helpers ----------------
__device__ __forceinline__ uint32_t smem_u32(const void* p) {
    uint32_t a;
    asm("{ .reg .u64 t; cvta.to.shared.u64 t, %1; cvt.u32.u64 %0, t; }"
        : "=r"(a) : "l"(p));
    return a;
}
__device__ __forceinline__ void ldsm_x4_t(uint32_t& r0, uint32_t& r1,
                                          uint32_t& r2, uint32_t& r3, uint32_t a) {
    asm volatile("ldmatrix.sync.aligned.m8n8.x4.trans.shared.b16 {%0,%1,%2,%3}, [%4];"
                 : "=r"(r0), "=r"(r1), "=r"(r2), "=r"(r3) : "r"(a));
}
__device__ __forceinline__ void mma_f16(float* c, const uint32_t* a, const uint32_t* b) {
    asm volatile("mma.sync.aligned.m16n8k16.row.col.f32.f16.f16.f32 "
                 "{%0,%1,%2,%3}, {%4,%5,%6,%7}, {%8,%9}, {%0,%1,%2,%3};"
                 : "+f"(c[0]), "+f"(c[1]), "+f"(c[2]), "+f"(c[3])
                 : "r"(a[0]), "r"(a[1]), "r"(a[2]), "r"(a[3]),
                   "r"(b[0]), "r"(b[1]));
}
__device__ __forceinline__ bool probe64(const void* e) {
    const int* p = (const int*)e;
    int acc = p[1] | p[3] | p[5] | p[7] | p[9] | p[11] | p[13] | p[15];
    return acc == 0;
}

// smem layout for GEMM
#define B_HI   0             // 128 rows * 272 B
#define SM_BIAS 34816
#define SM_SSUM 35328
#define SM_SSQ  35840
#define SMEMSZ  36352

// ---------------- kernel 1: prologue (x16 conv, wconv, zero deg+stats) ----
__global__ void prologue_kernel(const float* __restrict__ x,
                                const float* __restrict__ W_root,
                                const float* __restrict__ W_rel) {
    const int tid = threadIdx.x;
    const int idx = blockIdx.x * 256 + tid;
    const int n8 = (N_NODES * D) / 8;

    if (idx < n8) {
        const float4* src = (const float4*)x + idx * 2;
        float4 a = src[0], b = src[1];
        __half2 h0 = __halves2half2(__float2half_rn(a.x), __float2half_rn(a.y));
        __half2 h1 = __halves2half2(__float2half_rn(a.z), __float2half_rn(a.w));
        __half2 h2 = __halves2half2(__float2half_rn(b.x), __float2half_rn(b.y));
        __half2 h3 = __halves2half2(__float2half_rn(b.z), __float2half_rn(b.w));
        ((uint4*)g_x16)[idx] = make_uint4(*(uint32_t*)&h0, *(uint32_t*)&h1,
                                          *(uint32_t*)&h2, *(uint32_t*)&h3);
    }
    if (idx < 25000)
        ((int4*)g_deg)[idx] = make_int4(0, 0, 0, 0);

    if (idx < 8192) {
#pragma unroll
        for (int p = idx; p < 16384; p += 8192) {
            int k = p >> 6;
            int n2 = (p & 63) * 2;
            const float* W = (k < 128) ? (W_root + k * 128 + n2)
                                       : (W_rel + (k - 128) * 128 + n2);
            float2 v = *(const float2*)W;
            __half2 h = __halves2half2(__float2half_rn(v.x), __float2half_rn(v.y));
            *(uint32_t*)((char*)gW_h + (size_t)(k * 128 + n2) * 2) = *(uint32_t*)&h;
        }
    }
    if (blockIdx.x == 0 && tid < D) { g_sum[tid] = 0.f; g_sumsq[tid] = 0.f; }
}

// ---------------- kernel 2: degree histogram ----------------
__global__ void hist_kernel(const void* __restrict__ eidx) {
    const bool is64 = probe64(eidx);
    int base = (blockIdx.x * 256 + threadIdx.x) * 4;
    if (base >= N_EDGES) return;
    int d[4];
    if (is64) {
        const long long* e = (const long long*)eidx + N_EDGES + base;
        d[0] = (int)e[0]; d[1] = (int)e[1]; d[2] = (int)e[2]; d[3] = (int)e[3];
    } else {
        int4 v = *(const int4*)((const int*)eidx + N_EDGES + base);
        d[0] = v.x; d[1] = v.y; d[2] = v.z; d[3] = v.w;
    }
#pragma unroll
    for (int j = 0; j < 4; j++)
        if (base + j < N_EDGES && (unsigned)d[j] < N_NODES)
            atomicAdd(&g_deg[d[j]], 1);
}

// ---------------- kernel 3a: per-block degree sums ----------------
__global__ void scanA_kernel() {
    __shared__ int s[256];
    int i = blockIdx.x * 256 + threadIdx.x;
    s[threadIdx.x] = (i < N_NODES) ? g_deg[i] : 0;
    __syncthreads();
#pragma unroll
    for (int off = 128; off > 0; off >>= 1) {
        if (threadIdx.x < off) s[threadIdx.x] += s[threadIdx.x + off];
        __syncthreads();
    }
    if (threadIdx.x == 0) g_part[blockIdx.x] = s[0];
}

// ---------------- kernel 3b: block scan + inline partial-prefix ----------
__global__ void scanC_kernel() {
    __shared__ int s[256];
    __shared__ int red[256];
    int t = threadIdx.x;
    int i = blockIdx.x * 256 + t;

    int p = 0;
    if (t < NSCAN && t < blockIdx.x) p = g_part[t];
    if (t + 256 < NSCAN && t + 256 < blockIdx.x) p += g_part[t + 256];
    red[t] = p;
    __syncthreads();
#pragma unroll
    for (int off = 128; off > 0; off >>= 1) {
        if (t < off) red[t] += red[t + off];
        __syncthreads();
    }
    const int blockoff = red[0];

    int v = (i < N_NODES) ? g_deg[i] : 0;
    s[t] = v;
    __syncthreads();
#pragma unroll
    for (int off = 1; off < 256; off <<= 1) {
        int add = (t >= off) ? s[t - off] : 0;
        __syncthreads();
        s[t] += add;
        __syncthreads();
    }
    if (i < N_NODES) {
        int excl = s[t] - v + blockoff;
        g_off[i] = excl;
        g_fill[i] = excl;
    }
    if (blockIdx.x == NSCAN - 1 && t == 255)
        g_off[N_NODES] = blockoff + s[255];
}

// ---------------- kernel 4: permute src ids into CSR slots ----------------
__global__ void permute_kernel(const void* __restrict__ eidx) {
    const bool is64 = probe64(eidx);
    int base = (blockIdx.x * 256 + threadIdx.x) * 4;
    if (base >= N_EDGES) return;
    int s[4], d[4];
    if (is64) {
        const long long* es = (const long long*)eidx + base;
        const long long* ed = (const long long*)eidx + N_EDGES + base;
        s[0] = (int)es[0]; s[1] = (int)es[1]; s[2] = (int)es[2]; s[3] = (int)es[3];
        d[0] = (int)ed[0]; d[1] = (int)ed[1]; d[2] = (int)ed[2]; d[3] = (int)ed[3];
    } else {
        int4 sv = *(const int4*)((const int*)eidx + base);
        int4 dv = *(const int4*)((const int*)eidx + N_EDGES + base);
        s[0] = sv.x; s[1] = sv.y; s[2] = sv.z; s[3] = sv.w;
        d[0] = dv.x; d[1] = dv.y; d[2] = dv.z; d[3] = dv.w;
    }
#pragma unroll
    for (int j = 0; j < 4; j++) {
        if (base + j < N_EDGES && (unsigned)d[j] < N_NODES) {
            int pos = atomicAdd(&g_fill[d[j]], 1);
            g_perm[pos] = ((unsigned)s[j] < N_NODES) ? s[j] : 0;
        }
    }
}

// ---------------- kernel 5: aggregate (warp per node, MLP-8 gathers) ------
__global__ void __launch_bounds__(256, 4)
aggregate_kernel() {
    int warp = blockIdx.x * 8 + (threadIdx.x >> 5);
    if (warp >= N_NODES) return;
    int lane = threadIdx.x & 31;
    int start = g_off[warp];
    int cnt = g_off[warp + 1] - start;

    float4 acc = make_float4(0.f, 0.f, 0.f, 0.f);
#pragma unroll 1
    for (int base = 0; base < cnt; base += 32) {
        int nrem = min(32, cnt - base);
        int my = (lane < nrem) ? g_perm[start + base + lane] : 0;
#pragma unroll 1
        for (int g = 0; g < nrem; g += 8) {
            int nb = min(8, nrem - g);
            uint2 h[8];
#pragma unroll
            for (int k = 0; k < 8; k++) {
                int sidx = __shfl_sync(0xffffffffu, my, g + k);
                h[k] = (k < nb)
                     ? *((const uint2*)(g_x16 + (size_t)sidx * D) + lane)
                     : make_uint2(0u, 0u);
            }
#pragma unroll
            for (int k = 0; k < 8; k++) {
                float2 f0 = __half22float2(*(__half2*)&h[k].x);
                float2 f1 = __half22float2(*(__half2*)&h[k].y);
                acc.x += f0.x; acc.y += f0.y; acc.z += f1.x; acc.w += f1.y;
            }
        }
    }
    __half2 o0 = __halves2half2(__float2half_rn(acc.x), __float2half_rn(acc.y));
    __half2 o1 = __halves2half2(__float2half_rn(acc.z), __float2half_rn(acc.w));
    *((uint2*)(g_aggr16 + (size_t)warp * D) + lane) =
        make_uint2(*(uint32_t*)&o0, *(uint32_t*)&o1);
}

// ---------------- kernel 6: K=256 fp16 GEMM + bias + BN stats -------------
// h = x16@W_root + aggr16@W_rel + b_rel ; h stored fp16, stats from fp32 acc
__global__ void __launch_bounds__(256, 2)
gemmAB_kernel(const float* __restrict__ b_rel) {
    extern __shared__ char smem[];
    const uint32_t sb = smem_u32(smem);
    const int tid = threadIdx.x;
    const int w = tid >> 5;
    const int lid = tid & 31;
    const int m0 = blockIdx.x * 128;

    if (tid < 128) {
        ((float*)(smem + SM_BIAS))[tid] = b_rel[tid];
        ((float*)(smem + SM_SSUM))[tid] = 0.f;
        ((float*)(smem + SM_SSQ))[tid]  = 0.f;
    }

    float acc[16][4];
#pragma unroll
    for (int q = 0; q < 16; q++)
#pragma unroll
        for (int c = 0; c < 4; c++) acc[q][c] = 0.f;

    const int r = lid >> 2;
    const int cq = (lid & 3) * 2;
    const int m = m0 + w * 16 + r;
    const bool v0 = m < N_NODES;
    const bool v1 = (m + 8) < N_NODES;

#pragma unroll 1
    for (int half = 0; half < 2; half++) {
#pragma unroll
        for (int i = 0; i < 8; i++) {
            int ch = tid + i * 256;
            int row = ch >> 4, c16 = ch & 15;
            size_t gsrc = (size_t)((half * 128 + row) * 128 + c16 * 8) * 2;
            *(uint4*)(smem + B_HI + row * 272 + c16 * 16) =
                *(const uint4*)((const char*)gW_h + gsrc);
        }
        __syncthreads();

        const __half* ph0 = (half ? g_aggr16 : g_x16) + (size_t)m * D + cq;
        const __half* ph1 = (half ? g_aggr16 : g_x16) + (size_t)(m + 8) * D + cq;
#pragma unroll
        for (int s = 0; s < 8; s++) {
            const int ko = s * 16;
            uint32_t ah[4];
            ah[0] = v0 ? *(const uint32_t*)(ph0 + ko)     : 0u;
            ah[1] = v1 ? *(const uint32_t*)(ph1 + ko)     : 0u;
            ah[2] = v0 ? *(const uint32_t*)(ph0 + ko + 8) : 0u;
            ah[3] = v1 ? *(const uint32_t*)(ph1 + ko + 8) : 0u;
            const uint32_t rowa = sb + (uint32_t)((s * 16 + (lid & 15)) * 272
                                                  + (lid >> 4) * 16);
#pragma unroll
            for (int q8 = 0; q8 < 8; q8++) {
                uint32_t bh[4];
                ldsm_x4_t(bh[0], bh[1], bh[2], bh[3],
                          rowa + (uint32_t)(q8 * 32) + B_HI);
                mma_f16(acc[q8 * 2],     ah, bh);
                mma_f16(acc[q8 * 2 + 1], ah, bh + 2);
            }
        }
        __syncthreads();
    }

    // ---- epilogue: bias + fp16 store + BN stats (shuffle-reduced) ----
    const float* bs = (const float*)(smem + SM_BIAS);
    float* ssum = (float*)(smem + SM_SSUM);
    float* ssq  = (float*)(smem + SM_SSQ);
#pragma unroll
    for (int q = 0; q < 16; q++) {
        int n = q * 8 + cq;
        float b0 = bs[n], b1 = bs[n + 1];
        float s0 = 0.f, s1 = 0.f, q0 = 0.f, q1 = 0.f;
        if (v0) {
            float ox = acc[q][0] + b0, oy = acc[q][1] + b1;
            __half2 oh = __halves2half2(__float2half_rn(ox), __float2half_rn(oy));
            *(uint32_t*)(g_h16 + (size_t)m * D + n) = *(uint32_t*)&oh;
            s0 += ox; s1 += oy;
            q0 += ox * ox; q1 += oy * oy;
        }
        if (v1) {
            float ox = acc[q][2] + b0, oy = acc[q][3] + b1;
            __half2 oh = __halves2half2(__float2half_rn(ox), __float2half_rn(oy));
            *(uint32_t*)(g_h16 + (size_t)(m + 8) * D + n) = *(uint32_t*)&oh;
            s0 += ox; s1 += oy;
            q0 += ox * ox; q1 += oy * oy;
        }
#pragma unroll
        for (int mk = 4; mk <= 16; mk <<= 1) {
            s0 += __shfl_xor_sync(0xffffffffu, s0, mk);
            s1 += __shfl_xor_sync(0xffffffffu, s1, mk);
            q0 += __shfl_xor_sync(0xffffffffu, q0, mk);
            q1 += __shfl_xor_sync(0xffffffffu, q1, mk);
        }
        if ((lid >> 2) == 0) {
            atomicAdd(&ssum[n],     s0);
            atomicAdd(&ssum[n + 1], s1);
            atomicAdd(&ssq[n],      q0);
            atomicAdd(&ssq[n + 1],  q1);
        }
    }
    __syncthreads();
    if (tid < 128) {
        atomicAdd(&g_sum[tid],   ssum[tid]);
        atomicAdd(&g_sumsq[tid], ssq[tid]);
    }
}

// ---------------- fused finalize + normalize + ReLU ----------------
__global__ void norm_kernel(const float* __restrict__ gamma,
                            const float* __restrict__ beta,
                            float* __restrict__ out) {
    __shared__ float ssc[D], ssh[D];
    int t = threadIdx.x;
    if (t < D) {
        float inv_n = 1.0f / (float)N_NODES;
        float mean = g_sum[t] * inv_n;
        float var = g_sumsq[t] * inv_n - mean * mean;
        float sc = gamma[t] * rsqrtf(var + EPS);
        ssc[t] = sc;
        ssh[t] = beta[t] - mean * sc;
    }
    __syncthreads();
    int idx = blockIdx.x * blockDim.x + t;
    const int n4 = (N_NODES * D) / 4;
    if (idx >= n4) return;
    int c4 = (idx & (D / 4 - 1)) * 4;
    uint2 hw = ((const uint2*)g_h16)[idx];
    float2 f0 = __half22float2(*(__half2*)&hw.x);
    float2 f1 = __half22float2(*(__half2*)&hw.y);
    float4 o;
    o.x = fmaxf(f0.x * ssc[c4 + 0] + ssh[c4 + 0], 0.f);
    o.y = fmaxf(f0.y * ssc[c4 + 1] + ssh[c4 + 1], 0.f);
    o.z = fmaxf(f1.x * ssc[c4 + 2] + ssh[c4 + 2], 0.f);
    o.w = fmaxf(f1.y * ssc[c4 + 3] + ssh[c4 + 3], 0.f);
    ((float4*)out)[idx] = o;
}

// ---------------- launch ----------------
extern "C" void kernel_launch(void* const* d_in, const int* in_sizes, int n_in,
                              void* d_out, int out_size) {
    const float* x      = (const float*)d_in[0];
    const void*  eidx   = d_in[1];
    const float* W_root = (const float*)d_in[2];
    const float* W_rel  = (const float*)d_in[3];
    const float* b_rel  = (const float*)d_in[4];
    const float* gamma  = (const float*)d_in[5];
    const float* beta   = (const float*)d_in[6];
    float*       out    = (float*)d_out;

    cudaFuncSetAttribute(gemmAB_kernel,
                         cudaFuncAttributeMaxDynamicSharedMemorySize, SMEMSZ);

    const int n8 = (N_NODES * D) / 8;
    prologue_kernel<<<(n8 + 255) / 256, 256>>>(x, W_root, W_rel);

    const int eblk = (N_EDGES / 4 + 255) / 256;
    hist_kernel<<<eblk, 256>>>(eidx);

    scanA_kernel<<<NSCAN, 256>>>();
    scanC_kernel<<<NSCAN, 256>>>();

    permute_kernel<<<eblk, 256>>>(eidx);

    aggregate_kernel<<<(N_NODES + 7) / 8, 256>>>();

    gemmAB_kernel<<<(N_NODES + 127) / 128, 256, SMEMSZ>>>(b_rel);

    const int n4 = (N_NODES * D) / 4;
    norm_kernel<<<(n4 + 255) / 256, 256>>>(gamma, beta, out);
}

// round 17
// speedup vs baseline: 1.5525x; 1.0146x over previous
#include <cuda_runtime.h>
#include <cuda_fp16.h>
#include <cstdint>

#define N_NODES 100000
#define N_EDGES 1600000
#define D 128
#define EPS 1e-5f
#define NSCAN 391              // ceil(100000/256)

// ---------------- scratch ----------------
// INVARIANT: g_deg is all-zero at entry to every kernel_launch execution.
// (zero-initialized at load; re-zeroed by aggregate_kernel each run)
__device__ __half g_aggr16[(size_t)N_NODES * D];
__device__ __half g_h16[(size_t)N_NODES * D];
__device__ __half g_x16[(size_t)N_NODES * D];
__device__ float g_sum[D];
__device__ float g_sumsq[D];
__device__ __half gW_h[256 * 128];   // rows 0-127 W_root, 128-255 W_rel
__device__ int g_deg[N_NODES];
__device__ int g_off[N_NODES + 1];
__device__ int g_fill[N_NODES];
__device__ int g_part[NSCAN];
__device__ int g_perm[N_EDGES];

// ---------------- helpers ----------------
__device__ __forceinline__ uint32_t smem_u32(const void* p) {
    uint32_t a;
    asm("{ .reg .u64 t; cvta.to.shared.u64 t, %1; cvt.u32.u64 %0, t; }"
        : "=r"(a) : "l"(p));
    return a;
}
__device__ __forceinline__ void ldsm_x4_t(uint32_t& r0, uint32_t& r1,
                                          uint32_t& r2, uint32_t& r3, uint32_t a) {
    asm volatile("ldmatrix.sync.aligned.m8n8.x4.trans.shared.b16 {%0,%1,%2,%3}, [%4];"
                 : "=r"(r0), "=r"(r1), "=r"(r2), "=r"(r3) : "r"(a));
}
__device__ __forceinline__ void mma_f16(float* c, const uint32_t* a, const uint32_t* b) {
    asm volatile("mma.sync.aligned.m16n8k16.row.col.f32.f16.f16.f32 "
                 "{%0,%1,%2,%3}, {%4,%5,%6,%7}, {%8,%9}, {%0,%1,%2,%3};"
                 : "+f"(c[0]), "+f"(c[1]), "+f"(c[2]), "+f"(c[3])
                 : "r"(a[0]), "r"(a[1]), "r"(a[2]), "r"(a[3]),
                   "r"(b[0]), "r"(b[1]));
}
__device__ __forceinline__ bool probe64(const void* e) {
    const int* p = (const int*)e;
    int acc = p[1] | p[3] | p[5] | p[7] | p[9] | p[11] | p[13] | p[15];
    return acc == 0;
}

// smem layout for GEMM
#define B_HI   0             // 128 rows * 272 B
#define SM_BIAS 34816
#define SM_SSUM 35328
#define SM_SSQ  35840
#define SMEMSZ  36352

// ---------------- kernel 1: fused prologue + degree histogram ------------
// grid = 6250 blocks (covers (N_NODES*D)/8 conversion threads)
//  - idx < n8: convert 8 x values -> g_x16
//  - idx < 8192: convert weights
//  - idx*4 < N_EDGES: degree histogram (g_deg pre-zeroed by invariant)
//  - block 0: zero stats
__global__ void prologue_kernel(const float* __restrict__ x,
                                const float* __restrict__ W_root,
                                const float* __restrict__ W_rel,
                                const void* __restrict__ eidx) {
    const int tid = threadIdx.x;
    const int idx = blockIdx.x * 256 + tid;
    const int n8 = (N_NODES * D) / 8;

    if (idx < n8) {
        const float4* src = (const float4*)x + idx * 2;
        float4 a = src[0], b = src[1];
        __half2 h0 = __halves2half2(__float2half_rn(a.x), __float2half_rn(a.y));
        __half2 h1 = __halves2half2(__float2half_rn(a.z), __float2half_rn(a.w));
        __half2 h2 = __halves2half2(__float2half_rn(b.x), __float2half_rn(b.y));
        __half2 h3 = __halves2half2(__float2half_rn(b.z), __float2half_rn(b.w));
        ((uint4*)g_x16)[idx] = make_uint4(*(uint32_t*)&h0, *(uint32_t*)&h1,
                                          *(uint32_t*)&h2, *(uint32_t*)&h3);
    }

    if (idx < 8192) {
#pragma unroll
        for (int p = idx; p < 16384; p += 8192) {
            int k = p >> 6;
            int n2 = (p & 63) * 2;
            const float* W = (k < 128) ? (W_root + k * 128 + n2)
                                       : (W_rel + (k - 128) * 128 + n2);
            float2 v = *(const float2*)W;
            __half2 h = __halves2half2(__float2half_rn(v.x), __float2half_rn(v.y));
            *(uint32_t*)((char*)gW_h + (size_t)(k * 128 + n2) * 2) = *(uint32_t*)&h;
        }
    }

    // histogram: 4 edges per thread
    {
        int base = idx * 4;
        if (base < N_EDGES) {
            const bool is64 = probe64(eidx);
            int d[4];
            if (is64) {
                const long long* e = (const long long*)eidx + N_EDGES + base;
                d[0] = (int)e[0]; d[1] = (int)e[1];
                d[2] = (int)e[2]; d[3] = (int)e[3];
            } else {
                int4 v = *(const int4*)((const int*)eidx + N_EDGES + base);
                d[0] = v.x; d[1] = v.y; d[2] = v.z; d[3] = v.w;
            }
#pragma unroll
            for (int j = 0; j < 4; j++)
                if (base + j < N_EDGES && (unsigned)d[j] < N_NODES)
                    atomicAdd(&g_deg[d[j]], 1);
        }
    }

    if (blockIdx.x == 0 && tid < D) { g_sum[tid] = 0.f; g_sumsq[tid] = 0.f; }
}

// ---------------- kernel 2a: per-block degree sums ----------------
__global__ void scanA_kernel() {
    __shared__ int s[256];
    int i = blockIdx.x * 256 + threadIdx.x;
    s[threadIdx.x] = (i < N_NODES) ? g_deg[i] : 0;
    __syncthreads();
#pragma unroll
    for (int off = 128; off > 0; off >>= 1) {
        if (threadIdx.x < off) s[threadIdx.x] += s[threadIdx.x + off];
        __syncthreads();
    }
    if (threadIdx.x == 0) g_part[blockIdx.x] = s[0];
}

// ---------------- kernel 2b: block scan + inline partial-prefix ----------
__global__ void scanC_kernel() {
    __shared__ int s[256];
    __shared__ int red[256];
    int t = threadIdx.x;
    int i = blockIdx.x * 256 + t;

    int p = 0;
    if (t < NSCAN && t < blockIdx.x) p = g_part[t];
    if (t + 256 < NSCAN && t + 256 < blockIdx.x) p += g_part[t + 256];
    red[t] = p;
    __syncthreads();
#pragma unroll
    for (int off = 128; off > 0; off >>= 1) {
        if (t < off) red[t] += red[t + off];
        __syncthreads();
    }
    const int blockoff = red[0];

    int v = (i < N_NODES) ? g_deg[i] : 0;
    s[t] = v;
    __syncthreads();
#pragma unroll
    for (int off = 1; off < 256; off <<= 1) {
        int add = (t >= off) ? s[t - off] : 0;
        __syncthreads();
        s[t] += add;
        __syncthreads();
    }
    if (i < N_NODES) {
        int excl = s[t] - v + blockoff;
        g_off[i] = excl;
        g_fill[i] = excl;
    }
    if (blockIdx.x == NSCAN - 1 && t == 255)
        g_off[N_NODES] = blockoff + s[255];
}

// ---------------- kernel 3: permute src ids into CSR slots ----------------
__global__ void permute_kernel(const void* __restrict__ eidx) {
    const bool is64 = probe64(eidx);
    int base = (blockIdx.x * 256 + threadIdx.x) * 4;
    if (base >= N_EDGES) return;
    int s[4], d[4];
    if (is64) {
        const long long* es = (const long long*)eidx + base;
        const long long* ed = (const long long*)eidx + N_EDGES + base;
        s[0] = (int)es[0]; s[1] = (int)es[1]; s[2] = (int)es[2]; s[3] = (int)es[3];
        d[0] = (int)ed[0]; d[1] = (int)ed[1]; d[2] = (int)ed[2]; d[3] = (int)ed[3];
    } else {
        int4 sv = *(const int4*)((const int*)eidx + base);
        int4 dv = *(const int4*)((const int*)eidx + N_EDGES + base);
        s[0] = sv.x; s[1] = sv.y; s[2] = sv.z; s[3] = sv.w;
        d[0] = dv.x; d[1] = dv.y; d[2] = dv.z; d[3] = dv.w;
    }
#pragma unroll
    for (int j = 0; j < 4; j++) {
        if (base + j < N_EDGES && (unsigned)d[j] < N_NODES) {
            int pos = atomicAdd(&g_fill[d[j]], 1);
            g_perm[pos] = ((unsigned)s[j] < N_NODES) ? s[j] : 0;
        }
    }
}

// ---------------- kernel 4: aggregate + re-zero g_deg for next replay -----
__global__ void __launch_bounds__(256, 4)
aggregate_kernel() {
    // restore the g_deg==0 invariant for the next graph replay
    {
        int nid = blockIdx.x * 8 + (threadIdx.x & 7);
        if ((threadIdx.x >> 3) == 0 && nid < N_NODES) g_deg[nid] = 0;
    }

    int warp = blockIdx.x * 8 + (threadIdx.x >> 5);
    if (warp >= N_NODES) return;
    int lane = threadIdx.x & 31;
    int start = g_off[warp];
    int cnt = g_off[warp + 1] - start;

    float4 acc = make_float4(0.f, 0.f, 0.f, 0.f);
#pragma unroll 1
    for (int base = 0; base < cnt; base += 32) {
        int nrem = min(32, cnt - base);
        int my = (lane < nrem) ? g_perm[start + base + lane] : 0;
#pragma unroll 1
        for (int g = 0; g < nrem; g += 8) {
            int nb = min(8, nrem - g);
            uint2 h[8];
#pragma unroll
            for (int k = 0; k < 8; k++) {
                int sidx = __shfl_sync(0xffffffffu, my, g + k);
                h[k] = (k < nb)
                     ? *((const uint2*)(g_x16 + (size_t)sidx * D) + lane)
                     : make_uint2(0u, 0u);
            }
#pragma unroll
            for (int k = 0; k < 8; k++) {
                float2 f0 = __half22float2(*(__half2*)&h[k].x);
                float2 f1 = __half22float2(*(__half2*)&h[k].y);
                acc.x += f0.x; acc.y += f0.y; acc.z += f1.x; acc.w += f1.y;
            }
        }
    }
    __half2 o0 = __halves2half2(__float2half_rn(acc.x), __float2half_rn(acc.y));
    __half2 o1 = __halves2half2(__float2half_rn(acc.z), __float2half_rn(acc.w));
    *((uint2*)(g_aggr16 + (size_t)warp * D) + lane) =
        make_uint2(*(uint32_t*)&o0, *(uint32_t*)&o1);
}

// ---------------- kernel 5: K=256 fp16 GEMM + bias + BN stats -------------
__global__ void __launch_bounds__(256, 2)
gemmAB_kernel(const float* __restrict__ b_rel) {
    extern __shared__ char smem[];
    const uint32_t sb = smem_u32(smem);
    const int tid = threadIdx.x;
    const int w = tid >> 5;
    const int lid = tid & 31;
    const int m0 = blockIdx.x * 128;

    if (tid < 128) {
        ((float*)(smem + SM_BIAS))[tid] = b_rel[tid];
        ((float*)(smem + SM_SSUM))[tid] = 0.f;
        ((float*)(smem + SM_SSQ))[tid]  = 0.f;
    }

    float acc[16][4];
#pragma unroll
    for (int q = 0; q < 16; q++)
#pragma unroll
        for (int c = 0; c < 4; c++) acc[q][c] = 0.f;

    const int r = lid >> 2;
    const int cq = (lid & 3) * 2;
    const int m = m0 + w * 16 + r;
    const bool v0 = m < N_NODES;
    const bool v1 = (m + 8) < N_NODES;

#pragma unroll 1
    for (int half = 0; half < 2; half++) {
#pragma unroll
        for (int i = 0; i < 8; i++) {
            int ch = tid + i * 256;
            int row = ch >> 4, c16 = ch & 15;
            size_t gsrc = (size_t)((half * 128 + row) * 128 + c16 * 8) * 2;
            *(uint4*)(smem + B_HI + row * 272 + c16 * 16) =
                *(const uint4*)((const char*)gW_h + gsrc);
        }
        __syncthreads();

        const __half* ph0 = (half ? g_aggr16 : g_x16) + (size_t)m * D + cq;
        const __half* ph1 = (half ? g_aggr16 : g_x16) + (size_t)(m + 8) * D + cq;
#pragma unroll
        for (int s = 0; s < 8; s++) {
            const int ko = s * 16;
            uint32_t ah[4];
            ah[0] = v0 ? *(const uint32_t*)(ph0 + ko)     : 0u;
            ah[1] = v1 ? *(const uint32_t*)(ph1 + ko)     : 0u;
            ah[2] = v0 ? *(const uint32_t*)(ph0 + ko + 8) : 0u;
            ah[3] = v1 ? *(const uint32_t*)(ph1 + ko + 8) : 0u;
            const uint32_t rowa = sb + (uint32_t)((s * 16 + (lid & 15)) * 272
                                                  + (lid >> 4) * 16);
#pragma unroll
            for (int q8 = 0; q8 < 8; q8++) {
                uint32_t bh[4];
                ldsm_x4_t(bh[0], bh[1], bh[2], bh[3],
                          rowa + (uint32_t)(q8 * 32) + B_HI);
                mma_f16(acc[q8 * 2],     ah, bh);
                mma_f16(acc[q8 * 2 + 1], ah, bh + 2);
            }
        }
        __syncthreads();
    }

    // ---- epilogue: bias + fp16 store + BN stats (shuffle-reduced) ----
    const float* bs = (const float*)(smem + SM_BIAS);
    float* ssum = (float*)(smem + SM_SSUM);
    float* ssq  = (float*)(smem + SM_SSQ);
#pragma unroll
    for (int q = 0; q < 16; q++) {
        int n = q * 8 + cq;
        float b0 = bs[n], b1 = bs[n + 1];
        float s0 = 0.f, s1 = 0.f, q0 = 0.f, q1 = 0.f;
        if (v0) {
            float ox = acc[q][0] + b0, oy = acc[q][1] + b1;
            __half2 oh = __halves2half2(__float2half_rn(ox), __float2half_rn(oy));
            *(uint32_t*)(g_h16 + (size_t)m * D + n) = *(uint32_t*)&oh;
            s0 += ox; s1 += oy;
            q0 += ox * ox; q1 += oy * oy;
        }
        if (v1) {
            float ox = acc[q][2] + b0, oy = acc[q][3] + b1;
            __half2 oh = __halves2half2(__float2half_rn(ox), __float2half_rn(oy));
            *(uint32_t*)(g_h16 + (size_t)(m + 8) * D + n) = *(uint32_t*)&oh;
            s0 += ox; s1 += oy;
            q0 += ox * ox; q1 += oy * oy;
        }
#pragma unroll
        for (int mk = 4; mk <= 16; mk <<= 1) {
            s0 += __shfl_xor_sync(0xffffffffu, s0, mk);
            s1 += __shfl_xor_sync(0xffffffffu, s1, mk);
            q0 += __shfl_xor_sync(0xffffffffu, q0, mk);
            q1 += __shfl_xor_sync(0xffffffffu, q1, mk);
        }
        if ((lid >> 2) == 0) {
            atomicAdd(&ssum[n],     s0);
            atomicAdd(&ssum[n + 1], s1);
            atomicAdd(&ssq[n],      q0);
            atomicAdd(&ssq[n + 1],  q1);
        }
    }
    __syncthreads();
    if (tid < 128) {
        atomicAdd(&g_sum[tid],   ssum[tid]);
        atomicAdd(&g_sumsq[tid], ssq[tid]);
    }
}

// ---------------- fused finalize + normalize + ReLU ----------------
__global__ void norm_kernel(const float* __restrict__ gamma,
                            const float* __restrict__ beta,
                            float* __restrict__ out) {
    __shared__ float ssc[D], ssh[D];
    int t = threadIdx.x;
    if (t < D) {
        float inv_n = 1.0f / (float)N_NODES;
        float mean = g_sum[t] * inv_n;
        float var = g_sumsq[t] * inv_n - mean * mean;
        float sc = gamma[t] * rsqrtf(var + EPS);
        ssc[t] = sc;
        ssh[t] = beta[t] - mean * sc;
    }
    __syncthreads();
    int idx = blockIdx.x * blockDim.x + t;
    const int n4 = (N_NODES * D) / 4;
    if (idx >= n4) return;
    int c4 = (idx & (D / 4 - 1)) * 4;
    uint2 hw = ((const uint2*)g_h16)[idx];
    float2 f0 = __half22float2(*(__half2*)&hw.x);
    float2 f1 = __half22float2(*(__half2*)&hw.y);
    float4 o;
    o.x = fmaxf(f0.x * ssc[c4 + 0] + ssh[c4 + 0], 0.f);
    o.y = fmaxf(f0.y * ssc[c4 + 1] + ssh[c4 + 1], 0.f);
    o.z = fmaxf(f1.x * ssc[c4 + 2] + ssh[c4 + 2], 0.f);
    o.w = fmaxf(f1.y * ssc[c4 + 3] + ssh[c4 + 3], 0.f);
    ((float4*)out)[idx] = o;
}

// ---------------- launch ----------------
extern "C" void kernel_launch(void* const* d_in, const int* in_sizes, int n_in,
                              void* d_out, int out_size) {
    const float* x      = (const float*)d_in[0];
    const void*  eidx   = d_in[1];
    const float* W_root = (const float*)d_in[2];
    const float* W_rel  = (const float*)d_in[3];
    const float* b_rel  = (const float*)d_in[4];
    const float* gamma  = (const float*)d_in[5];
    const float* beta   = (const float*)d_in[6];
    float*       out    = (float*)d_out;

    cudaFuncSetAttribute(gemmAB_kernel,
                         cudaFuncAttributeMaxDynamicSharedMemorySize, SMEMSZ);

    const int n8 = (N_NODES * D) / 8;
    prologue_kernel<<<(n8 + 255) / 256, 256>>>(x, W_root, W_rel, eidx);

    scanA_kernel<<<NSCAN, 256>>>();
    scanC_kernel<<<NSCAN, 256>>>();

    const int eblk = (N_EDGES / 4 + 255) / 256;
    permute_kernel<<<eblk, 256>>>(eidx);

    aggregate_kernel<<<(N_NODES + 7) / 8, 256>>>();

    gemmAB_kernel<<<(N_NODES + 127) / 128, 256, SMEMSZ>>>(b_rel);

    const int n4 = (N_NODES * D) / 4;
    norm_kernel<<<(n4 + 255) / 256, 256>>>(gamma, beta, out);
}